// round 1
// baseline (speedup 1.0000x reference)
#include <cuda_runtime.h>
#include <math.h>

// Problem constants
#define DMODEL 1024
#define NHEADS 16
#define DK     64
#define BATCH  4
#define SEQ    2048
#define MROWS  (BATCH * SEQ)   // 8192

// ---------------------------------------------------------------------------
// Scratch (no allocation allowed -> __device__ globals)
// ---------------------------------------------------------------------------
__device__ float g_Q[(size_t)MROWS * DMODEL];
__device__ float g_K[(size_t)MROWS * DMODEL];
__device__ float g_V[(size_t)MROWS * DMODEL];
__device__ float g_A[(size_t)MROWS * DMODEL];

// ---------------------------------------------------------------------------
// GEMM: C[M,N] = A[M,K] @ W[K,N] + bias[N]   (all row-major, fp32)
// Tiles: 128x128, K-tile 16, 256 threads, 8x8 per-thread microtile.
// ---------------------------------------------------------------------------
#define BM 128
#define BN 128
#define BKT 16

__global__ __launch_bounds__(256) void gemm_bias_kernel(
    const float* __restrict__ A, const float* __restrict__ W,
    const float* __restrict__ bias, float* __restrict__ C,
    int M, int N, int K)
{
    __shared__ float As[BKT][BM];   // transposed A tile: As[k][m]
    __shared__ float Bs[BKT][BN];

    const int tid = threadIdx.x;
    const int bx = blockIdx.x, by = blockIdx.y;
    const int tn = tid & 15, tm = tid >> 4;

    float acc[8][8];
#pragma unroll
    for (int i = 0; i < 8; ++i)
#pragma unroll
        for (int j = 0; j < 8; ++j) acc[i][j] = 0.f;

    const float* Ablk = A + (size_t)by * BM * K;
    const float* Wblk = W + bx * BN;

    for (int k0 = 0; k0 < K; k0 += BKT) {
        // A tile: 128 rows x 16 k  = 512 float4
#pragma unroll
        for (int i = tid; i < 512; i += 256) {
            int r = i >> 2, c = (i & 3) * 4;
            float4 a = *(const float4*)(Ablk + (size_t)r * K + k0 + c);
            As[c + 0][r] = a.x; As[c + 1][r] = a.y;
            As[c + 2][r] = a.z; As[c + 3][r] = a.w;
        }
        // B tile: 16 rows x 128 n = 512 float4
#pragma unroll
        for (int i = tid; i < 512; i += 256) {
            int r = i >> 5, c = (i & 31) * 4;
            *(float4*)(&Bs[r][c]) = *(const float4*)(Wblk + (size_t)(k0 + r) * N + c);
        }
        __syncthreads();

#pragma unroll
        for (int kk = 0; kk < BKT; ++kk) {
            float ra[8], rb[8];
            *(float4*)&ra[0] = *(const float4*)(&As[kk][tm * 8]);
            *(float4*)&ra[4] = *(const float4*)(&As[kk][tm * 8 + 4]);
            *(float4*)&rb[0] = *(const float4*)(&Bs[kk][tn * 8]);
            *(float4*)&rb[4] = *(const float4*)(&Bs[kk][tn * 8 + 4]);
#pragma unroll
            for (int i = 0; i < 8; ++i)
#pragma unroll
                for (int j = 0; j < 8; ++j)
                    acc[i][j] += ra[i] * rb[j];
        }
        __syncthreads();
    }

    float bv[8];
    *(float4*)&bv[0] = *(const float4*)(bias + bx * BN + tn * 8);
    *(float4*)&bv[4] = *(const float4*)(bias + bx * BN + tn * 8 + 4);
#pragma unroll
    for (int i = 0; i < 8; ++i) {
        float* crow = C + (size_t)(by * BM + tm * 8 + i) * N + bx * BN + tn * 8;
        float4 v0 = make_float4(acc[i][0] + bv[0], acc[i][1] + bv[1],
                                acc[i][2] + bv[2], acc[i][3] + bv[3]);
        float4 v1 = make_float4(acc[i][4] + bv[4], acc[i][5] + bv[5],
                                acc[i][6] + bv[6], acc[i][7] + bv[7]);
        *(float4*)(crow) = v0;
        *(float4*)(crow + 4) = v1;
    }
}

// ---------------------------------------------------------------------------
// Flash attention (fp32, online softmax).
// Block: 256 threads handles 64 query rows for one (b, h); streams K/V in
// 64-row tiles. Thread layout: 4 threads per q-row; thread g of a group owns
// k-columns [g*16, g*16+16) for scores and d-columns [g*16, g*16+16) for O.
// ---------------------------------------------------------------------------
#define QT 64
#define KT 64
#define LDP 72   // padded smem row stride (floats), 16B-aligned rows

__global__ __launch_bounds__(256) void flash_kernel(
    const float* __restrict__ Qg, const float* __restrict__ Kg,
    const float* __restrict__ Vg, float* __restrict__ Og)
{
    extern __shared__ float sh[];
    float* Qs = sh;                  // QT * LDP
    float* Ks = Qs + QT * LDP;       // KT * LDP
    float* Vs = Ks + KT * LDP;       // KT * LDP
    float* Ps = Vs + KT * LDP;       // QT * LDP

    const int b = blockIdx.z, h = blockIdx.y;
    const int q0 = blockIdx.x * QT;
    const int tid = threadIdx.x;
    const int qr = tid >> 2;   // q row within tile (0..63)
    const int g  = tid & 3;    // 16-wide chunk owner (0..3)

    const size_t base = ((size_t)b * SEQ) * DMODEL + (size_t)h * DK;

    // Load Q tile (64 x 64)
    for (int i = tid; i < QT * 16; i += 256) {
        int r = i >> 4, c = (i & 15) << 2;
        *(float4*)(Qs + r * LDP + c) =
            *(const float4*)(Qg + base + (size_t)(q0 + r) * DMODEL + c);
    }

    float o[16];
#pragma unroll
    for (int j = 0; j < 16; ++j) o[j] = 0.f;
    float m = -1e30f, l = 0.f;

    for (int k0 = 0; k0 < SEQ; k0 += KT) {
        // Load K,V tiles (64 x 64 each)
        for (int i = tid; i < KT * 16; i += 256) {
            int r = i >> 4, c = (i & 15) << 2;
            *(float4*)(Ks + r * LDP + c) =
                *(const float4*)(Kg + base + (size_t)(k0 + r) * DMODEL + c);
            *(float4*)(Vs + r * LDP + c) =
                *(const float4*)(Vg + base + (size_t)(k0 + r) * DMODEL + c);
        }
        __syncthreads();

        // Scores: s[j] = Q[qr,:] . K[g*16+j,:]
        float s[16];
#pragma unroll
        for (int j = 0; j < 16; ++j) s[j] = 0.f;
        const float* qrow  = Qs + qr * LDP;
        const float* kbase = Ks + (g * 16) * LDP;
#pragma unroll
        for (int d = 0; d < DK; d += 4) {
            float4 qv = *(const float4*)(qrow + d);
#pragma unroll
            for (int j = 0; j < 16; ++j) {
                float4 kv = *(const float4*)(kbase + j * LDP + d);
                s[j] += qv.x * kv.x + qv.y * kv.y + qv.z * kv.z + qv.w * kv.w;
            }
        }

        // Online softmax update (group of 4 threads per q row, same warp)
        float mx = -1e30f;
#pragma unroll
        for (int j = 0; j < 16; ++j) { s[j] *= 0.125f; mx = fmaxf(mx, s[j]); }
        mx = fmaxf(mx, __shfl_xor_sync(0xffffffffu, mx, 1));
        mx = fmaxf(mx, __shfl_xor_sync(0xffffffffu, mx, 2));
        float m_new = fmaxf(m, mx);
        float corr  = __expf(m - m_new);
        float lsum = 0.f;
        float* prow_w = Ps + qr * LDP + g * 16;
#pragma unroll
        for (int j = 0; j < 16; ++j) {
            float p = __expf(s[j] - m_new);
            prow_w[j] = p;
            lsum += p;
        }
        lsum += __shfl_xor_sync(0xffffffffu, lsum, 1);
        lsum += __shfl_xor_sync(0xffffffffu, lsum, 2);
        l = l * corr + lsum;
        m = m_new;
#pragma unroll
        for (int j = 0; j < 16; ++j) o[j] *= corr;
        __syncwarp();   // Ps row written/read within the same warp

        // O update: o[j] += sum_k P[qr,k] * V[k, g*16+j]
        const float* pr = Ps + qr * LDP;
        const float* vb = Vs + g * 16;
#pragma unroll
        for (int k = 0; k < KT; k += 4) {
            float4 pv = *(const float4*)(pr + k);
#pragma unroll
            for (int kk = 0; kk < 4; ++kk) {
                float p = (kk == 0) ? pv.x : (kk == 1) ? pv.y : (kk == 2) ? pv.z : pv.w;
                const float* vr = vb + (size_t)(k + kk) * LDP;
#pragma unroll
                for (int j = 0; j < 16; j += 4) {
                    float4 vv = *(const float4*)(vr + j);
                    o[j + 0] += p * vv.x; o[j + 1] += p * vv.y;
                    o[j + 2] += p * vv.z; o[j + 3] += p * vv.w;
                }
            }
        }
        __syncthreads();  // protect Ks/Vs/Ps before next tile's loads
    }

    float inv = 1.f / l;
    float* op = Og + base + (size_t)(q0 + qr) * DMODEL + g * 16;
#pragma unroll
    for (int j = 0; j < 16; j += 4) {
        float4 v = make_float4(o[j] * inv, o[j + 1] * inv,
                               o[j + 2] * inv, o[j + 3] * inv);
        *(float4*)(op + j) = v;
    }
}

// ---------------------------------------------------------------------------
// Launch
// ---------------------------------------------------------------------------
extern "C" void kernel_launch(void* const* d_in, const int* in_sizes, int n_in,
                              void* d_out, int out_size)
{
    const float* query = (const float*)d_in[0];
    const float* key   = (const float*)d_in[1];
    const float* value = (const float*)d_in[2];
    const float* Wq = (const float*)d_in[3];
    const float* bq = (const float*)d_in[4];
    const float* Wk = (const float*)d_in[5];
    const float* bk = (const float*)d_in[6];
    const float* Wv = (const float*)d_in[7];
    const float* bv = (const float*)d_in[8];
    const float* Wo = (const float*)d_in[9];
    const float* bo = (const float*)d_in[10];
    float* out = (float*)d_out;

    float *qbuf, *kbuf, *vbuf, *abuf;
    cudaGetSymbolAddress((void**)&qbuf, g_Q);
    cudaGetSymbolAddress((void**)&kbuf, g_K);
    cudaGetSymbolAddress((void**)&vbuf, g_V);
    cudaGetSymbolAddress((void**)&abuf, g_A);

    dim3 ggrid(DMODEL / BN, MROWS / BM);   // (8, 64)

    gemm_bias_kernel<<<ggrid, 256>>>(query, Wq, bq, qbuf, MROWS, DMODEL, DMODEL);
    gemm_bias_kernel<<<ggrid, 256>>>(key,   Wk, bk, kbuf, MROWS, DMODEL, DMODEL);
    gemm_bias_kernel<<<ggrid, 256>>>(value, Wv, bv, vbuf, MROWS, DMODEL, DMODEL);

    const int flash_smem = (QT + KT + KT + QT) * LDP * (int)sizeof(float); // 73728
    cudaFuncSetAttribute(flash_kernel,
                         cudaFuncAttributeMaxDynamicSharedMemorySize, flash_smem);
    dim3 fgrid(SEQ / QT, NHEADS, BATCH);   // (32, 16, 4)
    flash_kernel<<<fgrid, 256, flash_smem>>>(qbuf, kbuf, vbuf, abuf);

    gemm_bias_kernel<<<ggrid, 256>>>(abuf, Wo, bo, out, MROWS, DMODEL, DMODEL);
}

// round 3
// speedup vs baseline: 2.7392x; 2.7392x over previous
#include <cuda_runtime.h>
#include <math.h>

// Problem constants
#define DMODEL 1024
#define NHEADS 16
#define DK     64
#define BATCH  4
#define SEQ    2048
#define MROWS  (BATCH * SEQ)   // 8192

typedef unsigned long long ull;

// ---------------------------------------------------------------------------
// f32x2 packed-math helpers (Blackwell sm_103a packed fp32 pipe)
// ---------------------------------------------------------------------------
__device__ __forceinline__ void fma2(ull& d, ull a, ull b) {
    asm("fma.rn.f32x2 %0, %1, %2, %0;" : "+l"(d) : "l"(a), "l"(b));
}
__device__ __forceinline__ ull mul2(ull a, ull b) {
    ull r; asm("mul.rn.f32x2 %0, %1, %2;" : "=l"(r) : "l"(a), "l"(b)); return r;
}
__device__ __forceinline__ ull add2(ull a, ull b) {
    ull r; asm("add.rn.f32x2 %0, %1, %2;" : "=l"(r) : "l"(a), "l"(b)); return r;
}
__device__ __forceinline__ ull bc2(float x) {
    ull r; asm("mov.b64 %0, {%1, %1};" : "=l"(r) : "f"(x)); return r;
}
__device__ __forceinline__ float2 up2(ull a) {
    float2 f; asm("mov.b64 {%0, %1}, %2;" : "=f"(f.x), "=f"(f.y) : "l"(a)); return f;
}

// ---------------------------------------------------------------------------
// Scratch (no allocation allowed -> __device__ globals)
// ---------------------------------------------------------------------------
__device__ float g_Q[(size_t)MROWS * DMODEL];
__device__ float g_K[(size_t)MROWS * DMODEL];
__device__ float g_V[(size_t)MROWS * DMODEL];
__device__ float g_A[(size_t)MROWS * DMODEL];

// ---------------------------------------------------------------------------
// GEMM: C[M,N] = A[M,K] @ W[K,N] + bias[N]  (row-major fp32, f32x2 microkernel)
// 128x128 tile, K-tile 16, 256 threads, 8m x 8n per thread (n as 4 f32x2).
// Thread n-cols: {tn*4..tn*4+3} and {64+tn*4..+3}  (conflict-light LDS.128)
// ---------------------------------------------------------------------------
#define BM 128
#define BN 128
#define BKT 16

__global__ __launch_bounds__(256, 2) void gemm_bias_kernel(
    const float* __restrict__ A, const float* __restrict__ W,
    const float* __restrict__ bias, float* __restrict__ C,
    int M, int N, int K)
{
    __shared__ float As[BKT][132];   // transposed A tile: As[k][m], padded
    __shared__ float Bs[BKT][BN];

    const int tid = threadIdx.x;
    const int bx = blockIdx.x, by = blockIdx.y;
    const int tn = tid & 15, tm = tid >> 4;

    ull acc2[8][4];
#pragma unroll
    for (int i = 0; i < 8; ++i)
#pragma unroll
        for (int j = 0; j < 4; ++j) acc2[i][j] = 0ULL;

    const float* Ablk = A + (size_t)by * BM * K;
    const float* Wblk = W + bx * BN;

    for (int k0 = 0; k0 < K; k0 += BKT) {
        // A tile: 128 rows x 16 k  = 512 float4, transposed into As[k][m]
#pragma unroll
        for (int i = tid; i < 512; i += 256) {
            int r = i >> 2, c = (i & 3) * 4;
            float4 a = *(const float4*)(Ablk + (size_t)r * K + k0 + c);
            As[c + 0][r] = a.x; As[c + 1][r] = a.y;
            As[c + 2][r] = a.z; As[c + 3][r] = a.w;
        }
        // B tile: 16 rows x 128 n = 512 float4
#pragma unroll
        for (int i = tid; i < 512; i += 256) {
            int r = i >> 5, c = (i & 31) * 4;
            *(float4*)(&Bs[r][c]) = *(const float4*)(Wblk + (size_t)(k0 + r) * N + c);
        }
        __syncthreads();

#pragma unroll
        for (int kk = 0; kk < BKT; ++kk) {
            float4 af0 = *(const float4*)(&As[kk][tm * 8]);
            float4 af1 = *(const float4*)(&As[kk][tm * 8 + 4]);
            ulonglong2 b0 = *(const ulonglong2*)(&Bs[kk][tn * 4]);
            ulonglong2 b1 = *(const ulonglong2*)(&Bs[kk][64 + tn * 4]);
            ull a2[8];
            a2[0] = bc2(af0.x); a2[1] = bc2(af0.y);
            a2[2] = bc2(af0.z); a2[3] = bc2(af0.w);
            a2[4] = bc2(af1.x); a2[5] = bc2(af1.y);
            a2[6] = bc2(af1.z); a2[7] = bc2(af1.w);
#pragma unroll
            for (int i = 0; i < 8; ++i) {
                fma2(acc2[i][0], a2[i], b0.x);
                fma2(acc2[i][1], a2[i], b0.y);
                fma2(acc2[i][2], a2[i], b1.x);
                fma2(acc2[i][3], a2[i], b1.y);
            }
        }
        __syncthreads();
    }

    // bias, packed with identical half-ordering (loaded as ull from gmem)
    const float* bp = bias + bx * BN;
    ull bias2[4];
    bias2[0] = *(const ull*)(bp + tn * 4);
    bias2[1] = *(const ull*)(bp + tn * 4 + 2);
    bias2[2] = *(const ull*)(bp + 64 + tn * 4);
    bias2[3] = *(const ull*)(bp + 64 + tn * 4 + 2);

#pragma unroll
    for (int i = 0; i < 8; ++i) {
        float* crow = C + (size_t)(by * BM + tm * 8 + i) * N + bx * BN;
        ulonglong2 w;
        w.x = add2(acc2[i][0], bias2[0]);
        w.y = add2(acc2[i][1], bias2[1]);
        *(ulonglong2*)(crow + tn * 4) = w;
        w.x = add2(acc2[i][2], bias2[2]);
        w.y = add2(acc2[i][3], bias2[3]);
        *(ulonglong2*)(crow + 64 + tn * 4) = w;
    }
}

// ---------------------------------------------------------------------------
// Flash attention v2: 64q x 64k tiles, register microtiles, f32x2.
// Score phase:  thread (qg=tid>>4, kg=tid&15) owns q rows {qg+16i},
//               k rows {kg+16j} (4x4 scores), d-paired accumulation
//               (both operands natural float2 loads, zero packs).
// PV phase:     thread (qh=tid>>3, dg=tid&7) owns q rows {qh, qh+32},
//               d cols {dg*8..dg*8+7} (d-paired output, V natural float2).
// Softmax state (m, l, corr) lives in smem to bridge the two mappings.
// ---------------------------------------------------------------------------
#define FLD 68   // smem row stride (floats); rows 16B-aligned, banks step 4

__global__ __launch_bounds__(256, 2) void flash2_kernel(
    const float* __restrict__ Qg, const float* __restrict__ Kg,
    const float* __restrict__ Vg, float* __restrict__ Og)
{
    extern __shared__ float sh[];
    float* Qs = sh;                    // 64 * FLD
    float* Ks = Qs + 64 * FLD;
    float* Vs = Ks + 64 * FLD;
    float* Ps = Vs + 64 * FLD;
    float* sm_l    = Ps + 64 * FLD;    // 64
    float* sm_m    = sm_l + 64;        // 64
    float* sm_corr = sm_m + 64;        // 64

    const int b = blockIdx.z, h = blockIdx.y;
    const int q0 = blockIdx.x * 64;
    const int tid = threadIdx.x;
    const int kg = tid & 15, qg = tid >> 4;   // score mapping
    const int dg = tid & 7,  qh = tid >> 3;   // PV mapping

    const size_t base = ((size_t)b * SEQ) * DMODEL + (size_t)h * DK;

    // Load Q tile (64 x 64)
    {
        int r = tid >> 2, c0 = (tid & 3) << 4;
        const float* src = Qg + base + (size_t)(q0 + r) * DMODEL + c0;
        float* dst = Qs + r * FLD + c0;
#pragma unroll
        for (int u = 0; u < 4; ++u)
            *(float4*)(dst + u * 4) = *(const float4*)(src + u * 4);
    }
    if (tid < 64) { sm_l[tid] = 0.f; sm_m[tid] = -1e30f; }

    ull o2[2][4];
#pragma unroll
    for (int i = 0; i < 2; ++i)
#pragma unroll
        for (int j = 0; j < 4; ++j) o2[i][j] = 0ULL;

    for (int k0 = 0; k0 < SEQ; k0 += 64) {
        // Load K,V tiles (64 x 64 each)
        {
            int r = tid >> 2, c0 = (tid & 3) << 4;
            const float* ks = Kg + base + (size_t)(k0 + r) * DMODEL + c0;
            const float* vs = Vg + base + (size_t)(k0 + r) * DMODEL + c0;
            float* kd = Ks + r * FLD + c0;
            float* vd = Vs + r * FLD + c0;
#pragma unroll
            for (int u = 0; u < 4; ++u) {
                *(float4*)(kd + u * 4) = *(const float4*)(ks + u * 4);
                *(float4*)(vd + u * 4) = *(const float4*)(vs + u * 4);
            }
        }
        __syncthreads();

        // ---- Score phase: s2[i][j], d-paired (horizontal add at end) ----
        ull s2[4][4];
#pragma unroll
        for (int i = 0; i < 4; ++i)
#pragma unroll
            for (int j = 0; j < 4; ++j) s2[i][j] = 0ULL;

        const float* qp = Qs + qg * FLD;
        const float* kp = Ks + kg * FLD;
#pragma unroll
        for (int d = 0; d < DK; d += 4) {
            ulonglong2 qv[4], kv[4];
#pragma unroll
            for (int i = 0; i < 4; ++i)
                qv[i] = *(const ulonglong2*)(qp + i * 16 * FLD + d);
#pragma unroll
            for (int j = 0; j < 4; ++j)
                kv[j] = *(const ulonglong2*)(kp + j * 16 * FLD + d);
#pragma unroll
            for (int i = 0; i < 4; ++i)
#pragma unroll
                for (int j = 0; j < 4; ++j) {
                    fma2(s2[i][j], qv[i].x, kv[j].x);
                    fma2(s2[i][j], qv[i].y, kv[j].y);
                }
        }

        // ---- Softmax (per q row, 16 kg-lanes cooperate; same warp) ----
#pragma unroll
        for (int i = 0; i < 4; ++i) {
            float sc[4];
#pragma unroll
            for (int j = 0; j < 4; ++j) {
                float2 t = up2(s2[i][j]);
                sc[j] = (t.x + t.y) * 0.125f;   // 1/sqrt(64)
            }
            float mx = fmaxf(fmaxf(sc[0], sc[1]), fmaxf(sc[2], sc[3]));
            mx = fmaxf(mx, __shfl_xor_sync(0xffffffffu, mx, 1));
            mx = fmaxf(mx, __shfl_xor_sync(0xffffffffu, mx, 2));
            mx = fmaxf(mx, __shfl_xor_sync(0xffffffffu, mx, 4));
            mx = fmaxf(mx, __shfl_xor_sync(0xffffffffu, mx, 8));

            const int row = qg + 16 * i;
            const float mold = sm_m[row];
            const float mnew = fmaxf(mold, mx);
            float rs = 0.f;
            float p[4];
#pragma unroll
            for (int j = 0; j < 4; ++j) {
                p[j] = __expf(sc[j] - mnew);
                rs += p[j];
            }
            rs += __shfl_xor_sync(0xffffffffu, rs, 1);
            rs += __shfl_xor_sync(0xffffffffu, rs, 2);
            rs += __shfl_xor_sync(0xffffffffu, rs, 4);
            rs += __shfl_xor_sync(0xffffffffu, rs, 8);
            // shfls above are warp barriers -> all mold reads done before write
            if (kg == 0) {
                float corr = __expf(mold - mnew);
                sm_m[row] = mnew;
                sm_corr[row] = corr;
                sm_l[row] = sm_l[row] * corr + rs;
            }
#pragma unroll
            for (int j = 0; j < 4; ++j)
                Ps[row * FLD + kg + 16 * j] = p[j];
        }
        __syncthreads();

        // ---- PV phase: o2 += P @ V, d-paired, p broadcast-packed ----
        {
            const float* pr0 = Ps + qh * FLD;
            const float* pr1 = pr0 + 32 * FLD;
            ull c0_ = bc2(sm_corr[qh]);
            ull c1_ = bc2(sm_corr[qh + 32]);
#pragma unroll
            for (int j = 0; j < 4; ++j) {
                o2[0][j] = mul2(o2[0][j], c0_);
                o2[1][j] = mul2(o2[1][j], c1_);
            }
            const float* vb = Vs + dg * 8;
#pragma unroll 4
            for (int k = 0; k < 64; k += 4) {
                float4 p0 = *(const float4*)(pr0 + k);
                float4 p1 = *(const float4*)(pr1 + k);
                float pa0[4] = {p0.x, p0.y, p0.z, p0.w};
                float pa1[4] = {p1.x, p1.y, p1.z, p1.w};
#pragma unroll
                for (int kk = 0; kk < 4; ++kk) {
                    const float* vr = vb + (k + kk) * FLD;
                    ulonglong2 v0 = *(const ulonglong2*)(vr);
                    ulonglong2 v1 = *(const ulonglong2*)(vr + 4);
                    ull pb0 = bc2(pa0[kk]);
                    ull pb1 = bc2(pa1[kk]);
                    fma2(o2[0][0], pb0, v0.x); fma2(o2[0][1], pb0, v0.y);
                    fma2(o2[0][2], pb0, v1.x); fma2(o2[0][3], pb0, v1.y);
                    fma2(o2[1][0], pb1, v0.x); fma2(o2[1][1], pb1, v0.y);
                    fma2(o2[1][2], pb1, v1.x); fma2(o2[1][3], pb1, v1.y);
                }
            }
        }
        __syncthreads();
    }

    // Epilogue: normalize and store (d-pairs are contiguous -> direct ull store)
    ull i0 = bc2(1.f / sm_l[qh]);
    ull i1 = bc2(1.f / sm_l[qh + 32]);
    float* out0 = Og + base + (size_t)(q0 + qh) * DMODEL + dg * 8;
    float* out1 = Og + base + (size_t)(q0 + qh + 32) * DMODEL + dg * 8;
    ulonglong2 w;
    w.x = mul2(o2[0][0], i0); w.y = mul2(o2[0][1], i0);
    *(ulonglong2*)(out0) = w;
    w.x = mul2(o2[0][2], i0); w.y = mul2(o2[0][3], i0);
    *(ulonglong2*)(out0 + 4) = w;
    w.x = mul2(o2[1][0], i1); w.y = mul2(o2[1][1], i1);
    *(ulonglong2*)(out1) = w;
    w.x = mul2(o2[1][2], i1); w.y = mul2(o2[1][3], i1);
    *(ulonglong2*)(out1 + 4) = w;
}

// ---------------------------------------------------------------------------
// Launch
// ---------------------------------------------------------------------------
extern "C" void kernel_launch(void* const* d_in, const int* in_sizes, int n_in,
                              void* d_out, int out_size)
{
    const float* query = (const float*)d_in[0];
    const float* key   = (const float*)d_in[1];
    const float* value = (const float*)d_in[2];
    const float* Wq = (const float*)d_in[3];
    const float* bq = (const float*)d_in[4];
    const float* Wk = (const float*)d_in[5];
    const float* bk = (const float*)d_in[6];
    const float* Wv = (const float*)d_in[7];
    const float* bv = (const float*)d_in[8];
    const float* Wo = (const float*)d_in[9];
    const float* bo = (const float*)d_in[10];
    float* out = (float*)d_out;

    float *qbuf, *kbuf, *vbuf, *abuf;
    cudaGetSymbolAddress((void**)&qbuf, g_Q);
    cudaGetSymbolAddress((void**)&kbuf, g_K);
    cudaGetSymbolAddress((void**)&vbuf, g_V);
    cudaGetSymbolAddress((void**)&abuf, g_A);

    dim3 ggrid(DMODEL / BN, MROWS / BM);   // (8, 64)

    gemm_bias_kernel<<<ggrid, 256>>>(query, Wq, bq, qbuf, MROWS, DMODEL, DMODEL);
    gemm_bias_kernel<<<ggrid, 256>>>(key,   Wk, bk, kbuf, MROWS, DMODEL, DMODEL);
    gemm_bias_kernel<<<ggrid, 256>>>(value, Wv, bv, vbuf, MROWS, DMODEL, DMODEL);

    const int flash_smem = (4 * 64 * FLD + 3 * 64) * (int)sizeof(float); // 70400
    cudaFuncSetAttribute(flash2_kernel,
                         cudaFuncAttributeMaxDynamicSharedMemorySize, flash_smem);
    dim3 fgrid(SEQ / 64, NHEADS, BATCH);   // (32, 16, 4)
    flash2_kernel<<<fgrid, 256, flash_smem>>>(qbuf, kbuf, vbuf, abuf);

    gemm_bias_kernel<<<ggrid, 256>>>(abuf, Wo, bo, out, MROWS, DMODEL, DMODEL);
}

// round 7
// speedup vs baseline: 8.0967x; 2.9559x over previous
#include <cuda_runtime.h>
#include <cuda_bf16.h>

#define DMODEL 1024
#define NHEADS 16
#define DK     64
#define BATCH  4
#define SEQ    2048
#define MROWS  (BATCH * SEQ)              // 8192
#define SZ     ((size_t)MROWS * DMODEL)   // 8388608 elems
#define WSZ    ((size_t)DMODEL * DMODEL)

typedef unsigned int u32;
typedef unsigned short u16;
typedef __nv_bfloat16 bf16;

// ---------------------------------------------------------------------------
// Device scratch (no allocation allowed)
// ---------------------------------------------------------------------------
__device__ bf16 g_act[6 * SZ];   // [aq_h, aq_l, ak_h, ak_l, av_h, av_l]
__device__ bf16 g_prj[6 * SZ];   // [q_h, q_l, k_h, k_l, v_h, v_l]
__device__ bf16 g_o[2 * SZ];     // [o_h, o_l]
__device__ bf16 g_w[8 * WSZ];    // [wq_h, wq_l, wk_h, wk_l, wv_h, wv_l, wo_h, wo_l]

// ---------------------------------------------------------------------------
// PTX helpers (base-ISA only: ldmatrix + mma.sync, no tcgen05)
// ---------------------------------------------------------------------------
__device__ __forceinline__ u32 cvta_s(const void* p) {
    u32 a; asm("{ .reg .u64 t; cvta.to.shared.u64 t, %1; cvt.u32.u64 %0, t; }"
               : "=r"(a) : "l"(p)); return a;
}
__device__ __forceinline__ void sts128(u32 a, uint4 v) {
    asm volatile("st.shared.v4.b32 [%0], {%1,%2,%3,%4};"
                 :: "r"(a), "r"(v.x), "r"(v.y), "r"(v.z), "r"(v.w) : "memory");
}
#define SWZ(x) ((x) ^ (((x) >> 3) & 0x70))

__device__ __forceinline__ void ldmx4(u32& r0, u32& r1, u32& r2, u32& r3, u32 a) {
    asm volatile("ldmatrix.sync.aligned.m8n8.x4.shared.b16 {%0,%1,%2,%3}, [%4];"
                 : "=r"(r0), "=r"(r1), "=r"(r2), "=r"(r3) : "r"(a));
}
__device__ __forceinline__ void ldmx4t(u32& r0, u32& r1, u32& r2, u32& r3, u32 a) {
    asm volatile("ldmatrix.sync.aligned.m8n8.x4.trans.shared.b16 {%0,%1,%2,%3}, [%4];"
                 : "=r"(r0), "=r"(r1), "=r"(r2), "=r"(r3) : "r"(a));
}
__device__ __forceinline__ void mma16816(float* d, const u32* a, const u32* b) {
    asm volatile(
        "mma.sync.aligned.m16n8k16.row.col.f32.bf16.bf16.f32 "
        "{%0,%1,%2,%3}, {%4,%5,%6,%7}, {%8,%9}, {%0,%1,%2,%3};"
        : "+f"(d[0]), "+f"(d[1]), "+f"(d[2]), "+f"(d[3])
        : "r"(a[0]), "r"(a[1]), "r"(a[2]), "r"(a[3]), "r"(b[0]), "r"(b[1]));
}
__device__ __forceinline__ void split2(float v, u16& h, u16& l) {
    bf16 hb = __float2bfloat16_rn(v);
    h = *reinterpret_cast<u16*>(&hb);
    bf16 lb = __float2bfloat16_rn(v - __bfloat162float(hb));
    l = *reinterpret_cast<u16*>(&lb);
}
// pack (x0 -> low half, x1 -> high half) as hi and lo bf16x2
__device__ __forceinline__ void split_pack(float x0, float x1, u32& hp, u32& lp) {
    __nv_bfloat162 hh = __floats2bfloat162_rn(x0, x1);
    hp = *reinterpret_cast<u32*>(&hh);
    float r0 = x0 - __bfloat162float(hh.x);
    float r1 = x1 - __bfloat162float(hh.y);
    __nv_bfloat162 ll = __floats2bfloat162_rn(r0, r1);
    lp = *reinterpret_cast<u32*>(&ll);
}

// ---------------------------------------------------------------------------
// Conversion kernels
// ---------------------------------------------------------------------------
__global__ __launch_bounds__(256) void conv_split(
    const float* __restrict__ x, bf16* __restrict__ h, bf16* __restrict__ l, int n4)
{
    int i = blockIdx.x * 256 + threadIdx.x;
    if (i >= n4) return;
    float4 v = ((const float4*)x)[i];
    float vv[4] = {v.x, v.y, v.z, v.w};
    u16 hb[4], lb[4];
#pragma unroll
    for (int e = 0; e < 4; ++e) split2(vv[e], hb[e], lb[e]);
    ((uint2*)h)[i] = make_uint2(((u32)hb[1] << 16) | hb[0], ((u32)hb[3] << 16) | hb[2]);
    ((uint2*)l)[i] = make_uint2(((u32)lb[1] << 16) | lb[0], ((u32)lb[3] << 16) | lb[2]);
}

// W[k][n] fp32 -> Wt[n][k] split-bf16 (transpose through smem)
__global__ __launch_bounds__(256) void conv_wt(
    const float* __restrict__ W, bf16* __restrict__ Th, bf16* __restrict__ Tl)
{
    __shared__ float ts[32][33];
    int tx = threadIdx.x, ty = threadIdx.y;         // 32 x 8
    int x0 = blockIdx.x * 32, y0 = blockIdx.y * 32; // x: n, y: k
#pragma unroll
    for (int i = 0; i < 4; ++i)
        ts[ty + i * 8][tx] = W[(size_t)(y0 + ty + i * 8) * DMODEL + x0 + tx];
    __syncthreads();
#pragma unroll
    for (int i = 0; i < 4; ++i) {
        int n = x0 + ty + i * 8, k = y0 + tx;
        u16 h, l; split2(ts[tx][ty + i * 8], h, l);
        Th[(size_t)n * DMODEL + k] = *reinterpret_cast<bf16*>(&h);
        Tl[(size_t)n * DMODEL + k] = *reinterpret_cast<bf16*>(&l);
    }
}

// ---------------------------------------------------------------------------
// HMMA GEMM: C[m][n] = sum_k A[m][k]*Wt[n][k] + bias[n]
// Block 128x128, K-chunk 64, 8 warps (warp tile 64x32), split-bf16 3-product.
// Output fp32 (Cf) or split-bf16 (Ch, Cl).
// ---------------------------------------------------------------------------
__global__ __launch_bounds__(256, 1) void gemm_mma(
    const bf16* __restrict__ Ah, const bf16* __restrict__ Al,
    const bf16* __restrict__ Bh, const bf16* __restrict__ Bl,
    const float* __restrict__ bias,
    float* __restrict__ Cf, bf16* __restrict__ Ch, bf16* __restrict__ Cl)
{
    extern __shared__ char sm[];
    const u32 sb = cvta_s(sm);
    const u32 sAh = sb, sAl = sb + 16384, sBh = sb + 32768, sBl = sb + 49152;
    const int tid = threadIdx.x, wid = tid >> 5, lane = tid & 31;
    const int n0 = blockIdx.x * 128, m0 = blockIdx.y * 128;
    const int wm = (wid >> 2) * 64, wn = (wid & 3) * 32;

    float acc[4][4][4];
#pragma unroll
    for (int mi = 0; mi < 4; ++mi)
#pragma unroll
        for (int nt = 0; nt < 4; ++nt)
#pragma unroll
            for (int e = 0; e < 4; ++e) acc[mi][nt][e] = 0.f;

    for (int k0 = 0; k0 < DMODEL; k0 += 64) {
        // 128 rows x 64 cols per buffer = 1024 uint4 across 4 buffers
        // (256 threads x 4 iterations; row must stay < 128)
#pragma unroll
        for (int it = 0; it < 4; ++it) {
            int i = tid + it * 256;
            int row = i >> 3, c = i & 7;
            u32 so = SWZ((u32)(row * 128 + c * 16));
            size_t ao = (size_t)(m0 + row) * DMODEL + k0 + c * 8;
            size_t bo = (size_t)(n0 + row) * DMODEL + k0 + c * 8;
            sts128(sAh + so, *(const uint4*)(Ah + ao));
            sts128(sAl + so, *(const uint4*)(Al + ao));
            sts128(sBh + so, *(const uint4*)(Bh + bo));
            sts128(sBl + so, *(const uint4*)(Bl + bo));
        }
        __syncthreads();

#pragma unroll
        for (int ks = 0; ks < 4; ++ks) {
            u32 ah[4][4], al[4][4];
#pragma unroll
            for (int mi = 0; mi < 4; ++mi) {
                u32 ad = SWZ((u32)((wm + mi * 16 + (lane & 15)) * 128 +
                                   ks * 32 + (lane >> 4) * 16));
                ldmx4(ah[mi][0], ah[mi][1], ah[mi][2], ah[mi][3], sAh + ad);
                ldmx4(al[mi][0], al[mi][1], al[mi][2], al[mi][3], sAl + ad);
            }
            u32 bh[4][2], bl[4][2];
#pragma unroll
            for (int nj = 0; nj < 2; ++nj) {
                u32 ad = SWZ((u32)((wn + nj * 16 + (lane & 15)) * 128 +
                                   ks * 32 + (lane >> 4) * 16));
                u32 r0, r1, r2, r3;
                ldmx4(r0, r1, r2, r3, sBh + ad);
                bh[2 * nj][0] = r0; bh[2 * nj][1] = r2;
                bh[2 * nj + 1][0] = r1; bh[2 * nj + 1][1] = r3;
                ldmx4(r0, r1, r2, r3, sBl + ad);
                bl[2 * nj][0] = r0; bl[2 * nj][1] = r2;
                bl[2 * nj + 1][0] = r1; bl[2 * nj + 1][1] = r3;
            }
#pragma unroll
            for (int mi = 0; mi < 4; ++mi)
#pragma unroll
                for (int nt = 0; nt < 4; ++nt) {
                    mma16816(acc[mi][nt], ah[mi], bh[nt]);
                    mma16816(acc[mi][nt], ah[mi], bl[nt]);
                    mma16816(acc[mi][nt], al[mi], bh[nt]);
                }
        }
        __syncthreads();
    }

    const int g = lane >> 2, tq = lane & 3;
#pragma unroll
    for (int mi = 0; mi < 4; ++mi) {
        int row0 = m0 + wm + mi * 16 + g;
#pragma unroll
        for (int nt = 0; nt < 4; ++nt) {
            int col = n0 + wn + nt * 8 + tq * 2;
            float b0 = bias[col], b1 = bias[col + 1];
            float v00 = acc[mi][nt][0] + b0, v01 = acc[mi][nt][1] + b1;
            float v10 = acc[mi][nt][2] + b0, v11 = acc[mi][nt][3] + b1;
            if (Cf) {
                *(float2*)(Cf + (size_t)row0 * DMODEL + col) = make_float2(v00, v01);
                *(float2*)(Cf + (size_t)(row0 + 8) * DMODEL + col) = make_float2(v10, v11);
            } else {
                u32 hp, lp;
                split_pack(v00, v01, hp, lp);
                *(u32*)(Ch + (size_t)row0 * DMODEL + col) = hp;
                *(u32*)(Cl + (size_t)row0 * DMODEL + col) = lp;
                split_pack(v10, v11, hp, lp);
                *(u32*)(Ch + (size_t)(row0 + 8) * DMODEL + col) = hp;
                *(u32*)(Cl + (size_t)(row0 + 8) * DMODEL + col) = lp;
            }
        }
    }
}

// ---------------------------------------------------------------------------
// HMMA flash attention: 128 q rows per CTA (8 warps x 16 rows), 64-row
// kv tiles, split-bf16 3-product, max-free softmax. O accumulates in
// registers across all 32 kv tiles (no rescale). P frags are repacked from
// S accumulator frags directly (no P smem round-trip). V consumed via
// ldmatrix.x4.trans (no explicit transpose).
// ---------------------------------------------------------------------------
__global__ __launch_bounds__(256, 1) void flash_mma(
    const bf16* __restrict__ Qh_, const bf16* __restrict__ Ql_,
    const bf16* __restrict__ Kh_, const bf16* __restrict__ Kl_,
    const bf16* __restrict__ Vh_, const bf16* __restrict__ Vl_,
    bf16* __restrict__ Oh_, bf16* __restrict__ Ol_)
{
    extern __shared__ char sm[];
    const u32 sb = cvta_s(sm);
    const u32 sQh = sb,          sQl = sb + 16384;
    const u32 sKh = sb + 32768,  sKl = sb + 40960;
    const u32 sVh = sb + 49152,  sVl = sb + 57344;
    const int tid = threadIdx.x, wid = tid >> 5, lane = tid & 31;
    const int b = blockIdx.z, h = blockIdx.y, q0 = blockIdx.x * 128;
    const size_t base = ((size_t)b * SEQ) * DMODEL + (size_t)h * DK;

    // Load Q (128 x 64, hi+lo)
#pragma unroll
    for (int it = 0; it < 4; ++it) {
        int i = tid + it * 256;
        int row = i >> 3, c = i & 7;
        u32 so = SWZ((u32)(row * 128 + c * 16));
        size_t go = base + (size_t)(q0 + row) * DMODEL + c * 8;
        sts128(sQh + so, *(const uint4*)(Qh_ + go));
        sts128(sQl + so, *(const uint4*)(Ql_ + go));
    }
    __syncthreads();

    // Preload Q fragments for the whole kernel (Q smem is stable)
    u32 qh[4][4], ql[4][4];
#pragma unroll
    for (int ks = 0; ks < 4; ++ks) {
        u32 ad = SWZ((u32)((wid * 16 + (lane & 15)) * 128 +
                           ks * 32 + (lane >> 4) * 16));
        ldmx4(qh[ks][0], qh[ks][1], qh[ks][2], qh[ks][3], sQh + ad);
        ldmx4(ql[ks][0], ql[ks][1], ql[ks][2], ql[ks][3], sQl + ad);
    }

    float oc[8][4];
#pragma unroll
    for (int nt = 0; nt < 8; ++nt)
#pragma unroll
        for (int e = 0; e < 4; ++e) oc[nt][e] = 0.f;
    float rs0 = 0.f, rs1 = 0.f;

    for (int t = 0; t < 32; ++t) {
        __syncthreads();   // previous iteration's K/V reads complete
        const int k0v = t * 64;
#pragma unroll
        for (int it = 0; it < 2; ++it) {
            int i = tid + it * 256;
            int row = i >> 3, c = i & 7;
            u32 so = SWZ((u32)(row * 128 + c * 16));
            size_t go = base + (size_t)(k0v + row) * DMODEL + c * 8;
            sts128(sKh + so, *(const uint4*)(Kh_ + go));
            sts128(sKl + so, *(const uint4*)(Kl_ + go));
            sts128(sVh + so, *(const uint4*)(Vh_ + go));
            sts128(sVl + so, *(const uint4*)(Vl_ + go));
        }
        __syncthreads();

        // ---- S = Q K^T ----
        float sc[8][4];
#pragma unroll
        for (int nt = 0; nt < 8; ++nt)
#pragma unroll
            for (int e = 0; e < 4; ++e) sc[nt][e] = 0.f;

#pragma unroll
        for (int ks = 0; ks < 4; ++ks) {
            u32 kh[8][2], kl[8][2];
#pragma unroll
            for (int nj = 0; nj < 4; ++nj) {
                u32 ad = SWZ((u32)((nj * 16 + (lane & 15)) * 128 +
                                   ks * 32 + (lane >> 4) * 16));
                u32 r0, r1, r2, r3;
                ldmx4(r0, r1, r2, r3, sKh + ad);
                kh[2 * nj][0] = r0; kh[2 * nj][1] = r2;
                kh[2 * nj + 1][0] = r1; kh[2 * nj + 1][1] = r3;
                ldmx4(r0, r1, r2, r3, sKl + ad);
                kl[2 * nj][0] = r0; kl[2 * nj][1] = r2;
                kl[2 * nj + 1][0] = r1; kl[2 * nj + 1][1] = r3;
            }
#pragma unroll
            for (int nt = 0; nt < 8; ++nt) {
                mma16816(sc[nt], qh[ks], kh[nt]);
                mma16816(sc[nt], qh[ks], kl[nt]);
                mma16816(sc[nt], ql[ks], kh[nt]);
            }
        }

        // ---- exp (max-free) + row-sum accumulation ----
#pragma unroll
        for (int nt = 0; nt < 8; ++nt) {
#pragma unroll
            for (int e = 0; e < 4; ++e) sc[nt][e] = __expf(sc[nt][e] * 0.125f);
            rs0 += sc[nt][0] + sc[nt][1];
            rs1 += sc[nt][2] + sc[nt][3];
        }

        // ---- O += P V  (P repacked from S frags; V via ldmatrix.trans) ----
#pragma unroll
        for (int ks = 0; ks < 4; ++ks) {
            const int j0 = 2 * ks, j1 = 2 * ks + 1;
            u32 ph[4], pl[4];
            split_pack(sc[j0][0], sc[j0][1], ph[0], pl[0]);
            split_pack(sc[j0][2], sc[j0][3], ph[1], pl[1]);
            split_pack(sc[j1][0], sc[j1][1], ph[2], pl[2]);
            split_pack(sc[j1][2], sc[j1][3], ph[3], pl[3]);

            u32 vh[8][2], vl[8][2];
#pragma unroll
            for (int dj = 0; dj < 4; ++dj) {
                u32 ad = SWZ((u32)((ks * 16 + (lane & 15)) * 128 +
                                   dj * 32 + (lane >> 4) * 16));
                u32 r0, r1, r2, r3;
                ldmx4t(r0, r1, r2, r3, sVh + ad);
                vh[2 * dj][0] = r0; vh[2 * dj][1] = r1;
                vh[2 * dj + 1][0] = r2; vh[2 * dj + 1][1] = r3;
                ldmx4t(r0, r1, r2, r3, sVl + ad);
                vl[2 * dj][0] = r0; vl[2 * dj][1] = r1;
                vl[2 * dj + 1][0] = r2; vl[2 * dj + 1][1] = r3;
            }
#pragma unroll
            for (int nt = 0; nt < 8; ++nt) {
                mma16816(oc[nt], ph, vh[nt]);
                mma16816(oc[nt], ph, vl[nt]);
                mma16816(oc[nt], pl, vh[nt]);
            }
        }
    }

    // ---- epilogue: row-sum reduce, normalize, split-bf16 store ----
    rs0 += __shfl_xor_sync(0xffffffffu, rs0, 1);
    rs0 += __shfl_xor_sync(0xffffffffu, rs0, 2);
    rs1 += __shfl_xor_sync(0xffffffffu, rs1, 1);
    rs1 += __shfl_xor_sync(0xffffffffu, rs1, 2);
    const float inv0 = 1.f / rs0, inv1 = 1.f / rs1;

    const int g = lane >> 2, tq = lane & 3;
    const int row0 = q0 + wid * 16 + g;
#pragma unroll
    for (int nt = 0; nt < 8; ++nt) {
        int col = nt * 8 + tq * 2;
        u32 hp, lp;
        split_pack(oc[nt][0] * inv0, oc[nt][1] * inv0, hp, lp);
        *(u32*)(Oh_ + base + (size_t)row0 * DMODEL + col) = hp;
        *(u32*)(Ol_ + base + (size_t)row0 * DMODEL + col) = lp;
        split_pack(oc[nt][2] * inv1, oc[nt][3] * inv1, hp, lp);
        *(u32*)(Oh_ + base + (size_t)(row0 + 8) * DMODEL + col) = hp;
        *(u32*)(Ol_ + base + (size_t)(row0 + 8) * DMODEL + col) = lp;
    }
}

// ---------------------------------------------------------------------------
// Launch
// ---------------------------------------------------------------------------
extern "C" void kernel_launch(void* const* d_in, const int* in_sizes, int n_in,
                              void* d_out, int out_size)
{
    const float* query = (const float*)d_in[0];
    const float* key   = (const float*)d_in[1];
    const float* value = (const float*)d_in[2];
    const float* Wq = (const float*)d_in[3];
    const float* bq = (const float*)d_in[4];
    const float* Wk = (const float*)d_in[5];
    const float* bk = (const float*)d_in[6];
    const float* Wv = (const float*)d_in[7];
    const float* bv = (const float*)d_in[8];
    const float* Wo = (const float*)d_in[9];
    const float* bo = (const float*)d_in[10];
    float* out = (float*)d_out;

    bf16 *act, *prj, *obuf, *wbuf;
    cudaGetSymbolAddress((void**)&act,  g_act);
    cudaGetSymbolAddress((void**)&prj,  g_prj);
    cudaGetSymbolAddress((void**)&obuf, g_o);
    cudaGetSymbolAddress((void**)&wbuf, g_w);

    bf16 *aq_h = act,          *aq_l = act + SZ;
    bf16 *ak_h = act + 2 * SZ, *ak_l = act + 3 * SZ;
    bf16 *av_h = act + 4 * SZ, *av_l = act + 5 * SZ;
    bf16 *q_h = prj,          *q_l = prj + SZ;
    bf16 *k_h = prj + 2 * SZ, *k_l = prj + 3 * SZ;
    bf16 *v_h = prj + 4 * SZ, *v_l = prj + 5 * SZ;
    bf16 *o_h = obuf, *o_l = obuf + SZ;
    bf16 *wq_h = wbuf,           *wq_l = wbuf + WSZ;
    bf16 *wk_h = wbuf + 2 * WSZ, *wk_l = wbuf + 3 * WSZ;
    bf16 *wv_h = wbuf + 4 * WSZ, *wv_l = wbuf + 5 * WSZ;
    bf16 *wo_h = wbuf + 6 * WSZ, *wo_l = wbuf + 7 * WSZ;

    const int n4 = (int)(SZ / 4);
    conv_split<<<(n4 + 255) / 256, 256>>>(query, aq_h, aq_l, n4);
    conv_split<<<(n4 + 255) / 256, 256>>>(key,   ak_h, ak_l, n4);
    conv_split<<<(n4 + 255) / 256, 256>>>(value, av_h, av_l, n4);
    dim3 wtg(32, 32), wtb(32, 8);
    conv_wt<<<wtg, wtb>>>(Wq, wq_h, wq_l);
    conv_wt<<<wtg, wtb>>>(Wk, wk_h, wk_l);
    conv_wt<<<wtg, wtb>>>(Wv, wv_h, wv_l);
    conv_wt<<<wtg, wtb>>>(Wo, wo_h, wo_l);

    const int gsm = 65536;
    cudaFuncSetAttribute(gemm_mma, cudaFuncAttributeMaxDynamicSharedMemorySize, gsm);
    dim3 ggrid(DMODEL / 128, MROWS / 128);   // (8, 64)
    gemm_mma<<<ggrid, 256, gsm>>>(aq_h, aq_l, wq_h, wq_l, bq, nullptr, q_h, q_l);
    gemm_mma<<<ggrid, 256, gsm>>>(ak_h, ak_l, wk_h, wk_l, bk, nullptr, k_h, k_l);
    gemm_mma<<<ggrid, 256, gsm>>>(av_h, av_l, wv_h, wv_l, bv, nullptr, v_h, v_l);

    const int fsm = 65536;
    cudaFuncSetAttribute(flash_mma, cudaFuncAttributeMaxDynamicSharedMemorySize, fsm);
    dim3 fgrid(SEQ / 128, NHEADS, BATCH);    // (16, 16, 4)
    flash_mma<<<fgrid, 256, fsm>>>(q_h, q_l, k_h, k_l, v_h, v_l, o_h, o_l);

    gemm_mma<<<ggrid, 256, gsm>>>(o_h, o_l, wo_h, wo_l, bo, out, nullptr, nullptr);
}

// round 8
// speedup vs baseline: 10.3017x; 1.2723x over previous
#include <cuda_runtime.h>
#include <cuda_bf16.h>

#define DMODEL 1024
#define NHEADS 16
#define DK     64
#define BATCH  4
#define SEQ    2048
#define MROWS  (BATCH * SEQ)              // 8192
#define SZ     ((size_t)MROWS * DMODEL)   // 8388608 elems
#define WSZ    ((size_t)DMODEL * DMODEL)

typedef unsigned int u32;
typedef unsigned short u16;
typedef __nv_bfloat16 bf16;

// ---------------------------------------------------------------------------
// Device scratch (no allocation allowed)
// ---------------------------------------------------------------------------
__device__ bf16 g_act[6 * SZ];   // [aq_h, aq_l, ak_h, ak_l, av_h, av_l]
__device__ bf16 g_prj[6 * SZ];   // [q_h, q_l, k_h, k_l, v_h, v_l]
__device__ bf16 g_o[2 * SZ];     // [o_h, o_l]
__device__ bf16 g_w[8 * WSZ];    // [wq_h, wq_l, wk_h, wk_l, wv_h, wv_l, wo_h, wo_l]

// ---------------------------------------------------------------------------
// PTX helpers (base-ISA only: ldmatrix + mma.sync + cp.async)
// ---------------------------------------------------------------------------
__device__ __forceinline__ u32 cvta_s(const void* p) {
    u32 a; asm("{ .reg .u64 t; cvta.to.shared.u64 t, %1; cvt.u32.u64 %0, t; }"
               : "=r"(a) : "l"(p)); return a;
}
__device__ __forceinline__ void sts128(u32 a, uint4 v) {
    asm volatile("st.shared.v4.b32 [%0], {%1,%2,%3,%4};"
                 :: "r"(a), "r"(v.x), "r"(v.y), "r"(v.z), "r"(v.w) : "memory");
}
__device__ __forceinline__ void cpa16(u32 s, const void* g) {
    asm volatile("{ .reg .u64 gg; cvta.to.global.u64 gg, %1;"
                 "  cp.async.cg.shared.global [%0], [gg], 16; }"
                 :: "r"(s), "l"(g) : "memory");
}
__device__ __forceinline__ void cpcommit() { asm volatile("cp.async.commit_group;" ::: "memory"); }
__device__ __forceinline__ void cpwait1()  { asm volatile("cp.async.wait_group 1;" ::: "memory"); }
__device__ __forceinline__ void cpwait0()  { asm volatile("cp.async.wait_group 0;" ::: "memory"); }

#define SWZ(x) ((x) ^ (((x) >> 3) & 0x70))

__device__ __forceinline__ void ldmx4(u32& r0, u32& r1, u32& r2, u32& r3, u32 a) {
    asm volatile("ldmatrix.sync.aligned.m8n8.x4.shared.b16 {%0,%1,%2,%3}, [%4];"
                 : "=r"(r0), "=r"(r1), "=r"(r2), "=r"(r3) : "r"(a));
}
__device__ __forceinline__ void ldmx4t(u32& r0, u32& r1, u32& r2, u32& r3, u32 a) {
    asm volatile("ldmatrix.sync.aligned.m8n8.x4.trans.shared.b16 {%0,%1,%2,%3}, [%4];"
                 : "=r"(r0), "=r"(r1), "=r"(r2), "=r"(r3) : "r"(a));
}
__device__ __forceinline__ void mma16816(float* d, const u32* a, const u32* b) {
    asm volatile(
        "mma.sync.aligned.m16n8k16.row.col.f32.bf16.bf16.f32 "
        "{%0,%1,%2,%3}, {%4,%5,%6,%7}, {%8,%9}, {%0,%1,%2,%3};"
        : "+f"(d[0]), "+f"(d[1]), "+f"(d[2]), "+f"(d[3])
        : "r"(a[0]), "r"(a[1]), "r"(a[2]), "r"(a[3]), "r"(b[0]), "r"(b[1]));
}
__device__ __forceinline__ void split2(float v, u16& h, u16& l) {
    bf16 hb = __float2bfloat16_rn(v);
    h = *reinterpret_cast<u16*>(&hb);
    bf16 lb = __float2bfloat16_rn(v - __bfloat162float(hb));
    l = *reinterpret_cast<u16*>(&lb);
}
// pack (x0 -> low half, x1 -> high half) as hi and lo bf16x2
__device__ __forceinline__ void split_pack(float x0, float x1, u32& hp, u32& lp) {
    __nv_bfloat162 hh = __floats2bfloat162_rn(x0, x1);
    hp = *reinterpret_cast<u32*>(&hh);
    float r0 = x0 - __bfloat162float(hh.x);
    float r1 = x1 - __bfloat162float(hh.y);
    __nv_bfloat162 ll = __floats2bfloat162_rn(r0, r1);
    lp = *reinterpret_cast<u32*>(&ll);
}

// ---------------------------------------------------------------------------
// Conversion kernels
// ---------------------------------------------------------------------------
__global__ __launch_bounds__(256) void conv_split(
    const float* __restrict__ x, bf16* __restrict__ h, bf16* __restrict__ l, int n4)
{
    int i = blockIdx.x * 256 + threadIdx.x;
    if (i >= n4) return;
    float4 v = ((const float4*)x)[i];
    float vv[4] = {v.x, v.y, v.z, v.w};
    u16 hb[4], lb[4];
#pragma unroll
    for (int e = 0; e < 4; ++e) split2(vv[e], hb[e], lb[e]);
    ((uint2*)h)[i] = make_uint2(((u32)hb[1] << 16) | hb[0], ((u32)hb[3] << 16) | hb[2]);
    ((uint2*)l)[i] = make_uint2(((u32)lb[1] << 16) | lb[0], ((u32)lb[3] << 16) | lb[2]);
}

// W[k][n] fp32 -> Wt[n][k] split-bf16 (transpose through smem)
__global__ __launch_bounds__(256) void conv_wt(
    const float* __restrict__ W, bf16* __restrict__ Th, bf16* __restrict__ Tl)
{
    __shared__ float ts[32][33];
    int tx = threadIdx.x, ty = threadIdx.y;         // 32 x 8
    int x0 = blockIdx.x * 32, y0 = blockIdx.y * 32; // x: n, y: k
#pragma unroll
    for (int i = 0; i < 4; ++i)
        ts[ty + i * 8][tx] = W[(size_t)(y0 + ty + i * 8) * DMODEL + x0 + tx];
    __syncthreads();
#pragma unroll
    for (int i = 0; i < 4; ++i) {
        int n = x0 + ty + i * 8, k = y0 + tx;
        u16 h, l; split2(ts[tx][ty + i * 8], h, l);
        Th[(size_t)n * DMODEL + k] = *reinterpret_cast<bf16*>(&h);
        Tl[(size_t)n * DMODEL + k] = *reinterpret_cast<bf16*>(&l);
    }
}

// ---------------------------------------------------------------------------
// HMMA GEMM (cp.async 2-stage pipeline):
// C[m][n] = sum_k A[m][k]*Wt[n][k] + bias[n]
// Block 128x128, K-chunk 64, 8 warps (warp tile 64x32), split-bf16 3-product.
// smem: 2 stages x [Ah 16K][Al 16K][Bh 16K][Bl 16K] = 128 KB.
// ---------------------------------------------------------------------------
#define GEMM_ISSUE(st, k0) do {                                              \
    u32 bs_ = sb + (u32)(st) * 65536u;                                       \
    _Pragma("unroll")                                                        \
    for (int it_ = 0; it_ < 4; ++it_) {                                      \
        int i_ = tid + it_ * 256;                                            \
        int row_ = i_ >> 3, c_ = i_ & 7;                                     \
        u32 so_ = SWZ((u32)(row_ * 128 + c_ * 16));                          \
        size_t ao_ = (size_t)(m0 + row_) * DMODEL + (k0) + c_ * 8;           \
        size_t bo_ = (size_t)(n0 + row_) * DMODEL + (k0) + c_ * 8;           \
        cpa16(bs_ + so_,         Ah + ao_);                                  \
        cpa16(bs_ + 16384 + so_, Al + ao_);                                  \
        cpa16(bs_ + 32768 + so_, Bh + bo_);                                  \
        cpa16(bs_ + 49152 + so_, Bl + bo_);                                  \
    }                                                                        \
    cpcommit();                                                              \
} while (0)

__global__ __launch_bounds__(256, 1) void gemm_mma(
    const bf16* __restrict__ Ah, const bf16* __restrict__ Al,
    const bf16* __restrict__ Bh, const bf16* __restrict__ Bl,
    const float* __restrict__ bias,
    float* __restrict__ Cf, bf16* __restrict__ Ch, bf16* __restrict__ Cl)
{
    extern __shared__ char sm[];
    const u32 sb = cvta_s(sm);
    const int tid = threadIdx.x, wid = tid >> 5, lane = tid & 31;
    const int n0 = blockIdx.x * 128, m0 = blockIdx.y * 128;
    const int wm = (wid >> 2) * 64, wn = (wid & 3) * 32;

    float acc[4][4][4];
#pragma unroll
    for (int mi = 0; mi < 4; ++mi)
#pragma unroll
        for (int nt = 0; nt < 4; ++nt)
#pragma unroll
            for (int e = 0; e < 4; ++e) acc[mi][nt][e] = 0.f;

    GEMM_ISSUE(0, 0);

    for (int kc = 0; kc < 16; ++kc) {
        if (kc < 15) GEMM_ISSUE((kc + 1) & 1, (kc + 1) * 64);
        if (kc < 15) cpwait1(); else cpwait0();
        __syncthreads();

        const u32 bs = sb + (u32)(kc & 1) * 65536u;
        const u32 sAh = bs, sAl = bs + 16384, sBh = bs + 32768, sBl = bs + 49152;

#pragma unroll
        for (int ks = 0; ks < 4; ++ks) {
            u32 ah[4][4], al[4][4];
#pragma unroll
            for (int mi = 0; mi < 4; ++mi) {
                u32 ad = SWZ((u32)((wm + mi * 16 + (lane & 15)) * 128 +
                                   ks * 32 + (lane >> 4) * 16));
                ldmx4(ah[mi][0], ah[mi][1], ah[mi][2], ah[mi][3], sAh + ad);
                ldmx4(al[mi][0], al[mi][1], al[mi][2], al[mi][3], sAl + ad);
            }
            u32 bh[4][2], bl[4][2];
#pragma unroll
            for (int nj = 0; nj < 2; ++nj) {
                u32 ad = SWZ((u32)((wn + nj * 16 + (lane & 15)) * 128 +
                                   ks * 32 + (lane >> 4) * 16));
                u32 r0, r1, r2, r3;
                ldmx4(r0, r1, r2, r3, sBh + ad);
                bh[2 * nj][0] = r0; bh[2 * nj][1] = r2;
                bh[2 * nj + 1][0] = r1; bh[2 * nj + 1][1] = r3;
                ldmx4(r0, r1, r2, r3, sBl + ad);
                bl[2 * nj][0] = r0; bl[2 * nj][1] = r2;
                bl[2 * nj + 1][0] = r1; bl[2 * nj + 1][1] = r3;
            }
#pragma unroll
            for (int mi = 0; mi < 4; ++mi)
#pragma unroll
                for (int nt = 0; nt < 4; ++nt) {
                    mma16816(acc[mi][nt], ah[mi], bh[nt]);
                    mma16816(acc[mi][nt], ah[mi], bl[nt]);
                    mma16816(acc[mi][nt], al[mi], bh[nt]);
                }
        }
        __syncthreads();
    }

    const int g = lane >> 2, tq = lane & 3;
#pragma unroll
    for (int mi = 0; mi < 4; ++mi) {
        int row0 = m0 + wm + mi * 16 + g;
#pragma unroll
        for (int nt = 0; nt < 4; ++nt) {
            int col = n0 + wn + nt * 8 + tq * 2;
            float b0 = bias[col], b1 = bias[col + 1];
            float v00 = acc[mi][nt][0] + b0, v01 = acc[mi][nt][1] + b1;
            float v10 = acc[mi][nt][2] + b0, v11 = acc[mi][nt][3] + b1;
            if (Cf) {
                *(float2*)(Cf + (size_t)row0 * DMODEL + col) = make_float2(v00, v01);
                *(float2*)(Cf + (size_t)(row0 + 8) * DMODEL + col) = make_float2(v10, v11);
            } else {
                u32 hp, lp;
                split_pack(v00, v01, hp, lp);
                *(u32*)(Ch + (size_t)row0 * DMODEL + col) = hp;
                *(u32*)(Cl + (size_t)row0 * DMODEL + col) = lp;
                split_pack(v10, v11, hp, lp);
                *(u32*)(Ch + (size_t)(row0 + 8) * DMODEL + col) = hp;
                *(u32*)(Cl + (size_t)(row0 + 8) * DMODEL + col) = lp;
            }
        }
    }
}

// ---------------------------------------------------------------------------
// HMMA flash attention (cp.async 2-stage K/V pipeline): 128 q rows per CTA
// (8 warps x 16 rows), 64-row kv tiles, split-bf16 3-product, max-free
// softmax, O accumulated in registers across all 32 kv tiles.
// smem: Q 32K resident + 2 stages x [Kh 8K][Kl 8K][Vh 8K][Vl 8K] = 96 KB.
// ---------------------------------------------------------------------------
#define KV_ISSUE(st, t) do {                                                 \
    u32 bs_ = sb + 32768u + (u32)(st) * 32768u;                              \
    _Pragma("unroll")                                                        \
    for (int it_ = 0; it_ < 2; ++it_) {                                      \
        int i_ = tid + it_ * 256;                                            \
        int row_ = i_ >> 3, c_ = i_ & 7;                                     \
        u32 so_ = SWZ((u32)(row_ * 128 + c_ * 16));                          \
        size_t go_ = base + (size_t)((t) * 64 + row_) * DMODEL + c_ * 8;     \
        cpa16(bs_ + so_,         Kh_ + go_);                                 \
        cpa16(bs_ + 8192 + so_,  Kl_ + go_);                                 \
        cpa16(bs_ + 16384 + so_, Vh_ + go_);                                 \
        cpa16(bs_ + 24576 + so_, Vl_ + go_);                                 \
    }                                                                        \
    cpcommit();                                                              \
} while (0)

__global__ __launch_bounds__(256, 1) void flash_mma(
    const bf16* __restrict__ Qh_, const bf16* __restrict__ Ql_,
    const bf16* __restrict__ Kh_, const bf16* __restrict__ Kl_,
    const bf16* __restrict__ Vh_, const bf16* __restrict__ Vl_,
    bf16* __restrict__ Oh_, bf16* __restrict__ Ol_)
{
    extern __shared__ char sm[];
    const u32 sb = cvta_s(sm);
    const u32 sQh = sb, sQl = sb + 16384;
    const int tid = threadIdx.x, wid = tid >> 5, lane = tid & 31;
    const int b = blockIdx.z, h = blockIdx.y, q0 = blockIdx.x * 128;
    const size_t base = ((size_t)b * SEQ) * DMODEL + (size_t)h * DK;

    // Load Q (128 x 64, hi+lo), and prefetch first K/V tile
#pragma unroll
    for (int it = 0; it < 4; ++it) {
        int i = tid + it * 256;
        int row = i >> 3, c = i & 7;
        u32 so = SWZ((u32)(row * 128 + c * 16));
        size_t go = base + (size_t)(q0 + row) * DMODEL + c * 8;
        sts128(sQh + so, *(const uint4*)(Qh_ + go));
        sts128(sQl + so, *(const uint4*)(Ql_ + go));
    }
    KV_ISSUE(0, 0);
    __syncthreads();

    // Preload Q fragments for the whole kernel (Q smem is stable)
    u32 qh[4][4], ql[4][4];
#pragma unroll
    for (int ks = 0; ks < 4; ++ks) {
        u32 ad = SWZ((u32)((wid * 16 + (lane & 15)) * 128 +
                           ks * 32 + (lane >> 4) * 16));
        ldmx4(qh[ks][0], qh[ks][1], qh[ks][2], qh[ks][3], sQh + ad);
        ldmx4(ql[ks][0], ql[ks][1], ql[ks][2], ql[ks][3], sQl + ad);
    }

    float oc[8][4];
#pragma unroll
    for (int nt = 0; nt < 8; ++nt)
#pragma unroll
        for (int e = 0; e < 4; ++e) oc[nt][e] = 0.f;
    float rs0 = 0.f, rs1 = 0.f;

    for (int t = 0; t < 32; ++t) {
        if (t < 31) KV_ISSUE((t + 1) & 1, t + 1);
        if (t < 31) cpwait1(); else cpwait0();
        __syncthreads();

        const u32 bs = sb + 32768u + (u32)(t & 1) * 32768u;
        const u32 sKh = bs, sKl = bs + 8192, sVh = bs + 16384, sVl = bs + 24576;

        // ---- S = Q K^T ----
        float sc[8][4];
#pragma unroll
        for (int nt = 0; nt < 8; ++nt)
#pragma unroll
            for (int e = 0; e < 4; ++e) sc[nt][e] = 0.f;

#pragma unroll
        for (int ks = 0; ks < 4; ++ks) {
            u32 kh[8][2], kl[8][2];
#pragma unroll
            for (int nj = 0; nj < 4; ++nj) {
                u32 ad = SWZ((u32)((nj * 16 + (lane & 15)) * 128 +
                                   ks * 32 + (lane >> 4) * 16));
                u32 r0, r1, r2, r3;
                ldmx4(r0, r1, r2, r3, sKh + ad);
                kh[2 * nj][0] = r0; kh[2 * nj][1] = r2;
                kh[2 * nj + 1][0] = r1; kh[2 * nj + 1][1] = r3;
                ldmx4(r0, r1, r2, r3, sKl + ad);
                kl[2 * nj][0] = r0; kl[2 * nj][1] = r2;
                kl[2 * nj + 1][0] = r1; kl[2 * nj + 1][1] = r3;
            }
#pragma unroll
            for (int nt = 0; nt < 8; ++nt) {
                mma16816(sc[nt], qh[ks], kh[nt]);
                mma16816(sc[nt], qh[ks], kl[nt]);
                mma16816(sc[nt], ql[ks], kh[nt]);
            }
        }

        // ---- exp (max-free) + row-sum accumulation ----
#pragma unroll
        for (int nt = 0; nt < 8; ++nt) {
#pragma unroll
            for (int e = 0; e < 4; ++e) sc[nt][e] = __expf(sc[nt][e] * 0.125f);
            rs0 += sc[nt][0] + sc[nt][1];
            rs1 += sc[nt][2] + sc[nt][3];
        }

        // ---- O += P V  (P repacked from S frags; V via ldmatrix.trans) ----
#pragma unroll
        for (int ks = 0; ks < 4; ++ks) {
            const int j0 = 2 * ks, j1 = 2 * ks + 1;
            u32 ph[4], pl[4];
            split_pack(sc[j0][0], sc[j0][1], ph[0], pl[0]);
            split_pack(sc[j0][2], sc[j0][3], ph[1], pl[1]);
            split_pack(sc[j1][0], sc[j1][1], ph[2], pl[2]);
            split_pack(sc[j1][2], sc[j1][3], ph[3], pl[3]);

            u32 vh[8][2], vl[8][2];
#pragma unroll
            for (int dj = 0; dj < 4; ++dj) {
                u32 ad = SWZ((u32)((ks * 16 + (lane & 15)) * 128 +
                                   dj * 32 + (lane >> 4) * 16));
                u32 r0, r1, r2, r3;
                ldmx4t(r0, r1, r2, r3, sVh + ad);
                vh[2 * dj][0] = r0; vh[2 * dj][1] = r1;
                vh[2 * dj + 1][0] = r2; vh[2 * dj + 1][1] = r3;
                ldmx4t(r0, r1, r2, r3, sVl + ad);
                vl[2 * dj][0] = r0; vl[2 * dj][1] = r1;
                vl[2 * dj + 1][0] = r2; vl[2 * dj + 1][1] = r3;
            }
#pragma unroll
            for (int nt = 0; nt < 8; ++nt) {
                mma16816(oc[nt], ph, vh[nt]);
                mma16816(oc[nt], ph, vl[nt]);
                mma16816(oc[nt], pl, vh[nt]);
            }
        }
        __syncthreads();
    }

    // ---- epilogue: row-sum reduce, normalize, split-bf16 store ----
    rs0 += __shfl_xor_sync(0xffffffffu, rs0, 1);
    rs0 += __shfl_xor_sync(0xffffffffu, rs0, 2);
    rs1 += __shfl_xor_sync(0xffffffffu, rs1, 1);
    rs1 += __shfl_xor_sync(0xffffffffu, rs1, 2);
    const float inv0 = 1.f / rs0, inv1 = 1.f / rs1;

    const int g = lane >> 2, tq = lane & 3;
    const int row0 = q0 + wid * 16 + g;
#pragma unroll
    for (int nt = 0; nt < 8; ++nt) {
        int col = nt * 8 + tq * 2;
        u32 hp, lp;
        split_pack(oc[nt][0] * inv0, oc[nt][1] * inv0, hp, lp);
        *(u32*)(Oh_ + base + (size_t)row0 * DMODEL + col) = hp;
        *(u32*)(Ol_ + base + (size_t)row0 * DMODEL + col) = lp;
        split_pack(oc[nt][2] * inv1, oc[nt][3] * inv1, hp, lp);
        *(u32*)(Oh_ + base + (size_t)(row0 + 8) * DMODEL + col) = hp;
        *(u32*)(Ol_ + base + (size_t)(row0 + 8) * DMODEL + col) = lp;
    }
}

// ---------------------------------------------------------------------------
// Launch
// ---------------------------------------------------------------------------
extern "C" void kernel_launch(void* const* d_in, const int* in_sizes, int n_in,
                              void* d_out, int out_size)
{
    const float* query = (const float*)d_in[0];
    const float* key   = (const float*)d_in[1];
    const float* value = (const float*)d_in[2];
    const float* Wq = (const float*)d_in[3];
    const float* bq = (const float*)d_in[4];
    const float* Wk = (const float*)d_in[5];
    const float* bk = (const float*)d_in[6];
    const float* Wv = (const float*)d_in[7];
    const float* bv = (const float*)d_in[8];
    const float* Wo = (const float*)d_in[9];
    const float* bo = (const float*)d_in[10];
    float* out = (float*)d_out;

    bf16 *act, *prj, *obuf, *wbuf;
    cudaGetSymbolAddress((void**)&act,  g_act);
    cudaGetSymbolAddress((void**)&prj,  g_prj);
    cudaGetSymbolAddress((void**)&obuf, g_o);
    cudaGetSymbolAddress((void**)&wbuf, g_w);

    bf16 *aq_h = act,          *aq_l = act + SZ;
    bf16 *ak_h = act + 2 * SZ, *ak_l = act + 3 * SZ;
    bf16 *av_h = act + 4 * SZ, *av_l = act + 5 * SZ;
    bf16 *q_h = prj,          *q_l = prj + SZ;
    bf16 *k_h = prj + 2 * SZ, *k_l = prj + 3 * SZ;
    bf16 *v_h = prj + 4 * SZ, *v_l = prj + 5 * SZ;
    bf16 *o_h = obuf, *o_l = obuf + SZ;
    bf16 *wq_h = wbuf,           *wq_l = wbuf + WSZ;
    bf16 *wk_h = wbuf + 2 * WSZ, *wk_l = wbuf + 3 * WSZ;
    bf16 *wv_h = wbuf + 4 * WSZ, *wv_l = wbuf + 5 * WSZ;
    bf16 *wo_h = wbuf + 6 * WSZ, *wo_l = wbuf + 7 * WSZ;

    const int n4 = (int)(SZ / 4);
    conv_split<<<(n4 + 255) / 256, 256>>>(query, aq_h, aq_l, n4);
    conv_split<<<(n4 + 255) / 256, 256>>>(key,   ak_h, ak_l, n4);
    conv_split<<<(n4 + 255) / 256, 256>>>(value, av_h, av_l, n4);
    dim3 wtg(32, 32), wtb(32, 8);
    conv_wt<<<wtg, wtb>>>(Wq, wq_h, wq_l);
    conv_wt<<<wtg, wtb>>>(Wk, wk_h, wk_l);
    conv_wt<<<wtg, wtb>>>(Wv, wv_h, wv_l);
    conv_wt<<<wtg, wtb>>>(Wo, wo_h, wo_l);

    const int gsm = 131072;   // 2 stages x 64 KB
    cudaFuncSetAttribute(gemm_mma, cudaFuncAttributeMaxDynamicSharedMemorySize, gsm);
    dim3 ggrid(DMODEL / 128, MROWS / 128);   // (8, 64)
    gemm_mma<<<ggrid, 256, gsm>>>(aq_h, aq_l, wq_h, wq_l, bq, nullptr, q_h, q_l);
    gemm_mma<<<ggrid, 256, gsm>>>(ak_h, ak_l, wk_h, wk_l, bk, nullptr, k_h, k_l);
    gemm_mma<<<ggrid, 256, gsm>>>(av_h, av_l, wv_h, wv_l, bv, nullptr, v_h, v_l);

    const int fsm = 98304;    // Q 32 KB + 2 stages x 32 KB
    cudaFuncSetAttribute(flash_mma, cudaFuncAttributeMaxDynamicSharedMemorySize, fsm);
    dim3 fgrid(SEQ / 128, NHEADS, BATCH);    // (16, 16, 4)
    flash_mma<<<fgrid, 256, fsm>>>(q_h, q_l, k_h, k_l, v_h, v_l, o_h, o_l);

    gemm_mma<<<ggrid, 256, gsm>>>(o_h, o_l, wo_h, wo_l, bo, out, nullptr, nullptr);
}

// round 10
// speedup vs baseline: 12.2280x; 1.1870x over previous
#include <cuda_runtime.h>
#include <cuda_bf16.h>
#include <cuda_fp16.h>

#define DMODEL 1024
#define NHEADS 16
#define DK     64
#define BATCH  4
#define SEQ    2048
#define MROWS  (BATCH * SEQ)              // 8192
#define SZ     ((size_t)MROWS * DMODEL)   // 8388608 elems
#define WSZ    ((size_t)DMODEL * DMODEL)

typedef unsigned int u32;
typedef unsigned short u16;
typedef __nv_bfloat16 bf16;

// ---------------------------------------------------------------------------
// Device scratch (no allocation allowed)
// ---------------------------------------------------------------------------
__device__ bf16 g_act[6 * SZ];    // [aq_h, aq_l, ak_h, ak_l, av_h, av_l]
__device__ half g_prjh[4 * SZ];   // [q_h, q_l, k_h, v_h]  (fp16)
__device__ bf16 g_o[2 * SZ];      // [o_h, o_l]
__device__ bf16 g_w[8 * WSZ];     // [wq_h, wq_l, wk_h, wk_l, wv_h, wv_l, wo_h, wo_l]

// ---------------------------------------------------------------------------
// PTX helpers (base-ISA only: ldmatrix + mma.sync + cp.async)
// ---------------------------------------------------------------------------
__device__ __forceinline__ u32 cvta_s(const void* p) {
    u32 a; asm("{ .reg .u64 t; cvta.to.shared.u64 t, %1; cvt.u32.u64 %0, t; }"
               : "=r"(a) : "l"(p)); return a;
}
__device__ __forceinline__ void sts128(u32 a, uint4 v) {
    asm volatile("st.shared.v4.b32 [%0], {%1,%2,%3,%4};"
                 :: "r"(a), "r"(v.x), "r"(v.y), "r"(v.z), "r"(v.w) : "memory");
}
__device__ __forceinline__ void cpa16(u32 s, const void* g) {
    asm volatile("{ .reg .u64 gg; cvta.to.global.u64 gg, %1;"
                 "  cp.async.cg.shared.global [%0], [gg], 16; }"
                 :: "r"(s), "l"(g) : "memory");
}
__device__ __forceinline__ void cpcommit() { asm volatile("cp.async.commit_group;" ::: "memory"); }
__device__ __forceinline__ void cpwait1()  { asm volatile("cp.async.wait_group 1;" ::: "memory"); }
__device__ __forceinline__ void cpwait0()  { asm volatile("cp.async.wait_group 0;" ::: "memory"); }

#define SWZ(x) ((x) ^ (((x) >> 3) & 0x70))

__device__ __forceinline__ void ldmx4(u32& r0, u32& r1, u32& r2, u32& r3, u32 a) {
    asm volatile("ldmatrix.sync.aligned.m8n8.x4.shared.b16 {%0,%1,%2,%3}, [%4];"
                 : "=r"(r0), "=r"(r1), "=r"(r2), "=r"(r3) : "r"(a));
}
__device__ __forceinline__ void ldmx4t(u32& r0, u32& r1, u32& r2, u32& r3, u32 a) {
    asm volatile("ldmatrix.sync.aligned.m8n8.x4.trans.shared.b16 {%0,%1,%2,%3}, [%4];"
                 : "=r"(r0), "=r"(r1), "=r"(r2), "=r"(r3) : "r"(a));
}
// bf16 MMA
__device__ __forceinline__ void mma16816(float* d, const u32* a, const u32* b) {
    asm volatile(
        "mma.sync.aligned.m16n8k16.row.col.f32.bf16.bf16.f32 "
        "{%0,%1,%2,%3}, {%4,%5,%6,%7}, {%8,%9}, {%0,%1,%2,%3};"
        : "+f"(d[0]), "+f"(d[1]), "+f"(d[2]), "+f"(d[3])
        : "r"(a[0]), "r"(a[1]), "r"(a[2]), "r"(a[3]), "r"(b[0]), "r"(b[1]));
}
// fp16 MMA
__device__ __forceinline__ void mma16816h(float* d, const u32* a, const u32* b) {
    asm volatile(
        "mma.sync.aligned.m16n8k16.row.col.f32.f16.f16.f32 "
        "{%0,%1,%2,%3}, {%4,%5,%6,%7}, {%8,%9}, {%0,%1,%2,%3};"
        : "+f"(d[0]), "+f"(d[1]), "+f"(d[2]), "+f"(d[3])
        : "r"(a[0]), "r"(a[1]), "r"(a[2]), "r"(a[3]), "r"(b[0]), "r"(b[1]));
}
__device__ __forceinline__ void split2(float v, u16& h, u16& l) {
    bf16 hb = __float2bfloat16_rn(v);
    h = *reinterpret_cast<u16*>(&hb);
    bf16 lb = __float2bfloat16_rn(v - __bfloat162float(hb));
    l = *reinterpret_cast<u16*>(&lb);
}
// bf16x2 packers
__device__ __forceinline__ void split_pack(float x0, float x1, u32& hp, u32& lp) {
    __nv_bfloat162 hh = __floats2bfloat162_rn(x0, x1);
    hp = *reinterpret_cast<u32*>(&hh);
    float r0 = x0 - __bfloat162float(hh.x);
    float r1 = x1 - __bfloat162float(hh.y);
    __nv_bfloat162 ll = __floats2bfloat162_rn(r0, r1);
    lp = *reinterpret_cast<u32*>(&ll);
}
// fp16x2 packers (x0 -> low half)
__device__ __forceinline__ u32 pack2h(float x0, float x1) {
    __half2 hh = __floats2half2_rn(x0, x1);
    return *reinterpret_cast<u32*>(&hh);
}
__device__ __forceinline__ void split_pack_h(float x0, float x1, u32& hp, u32& lp) {
    __half2 hh = __floats2half2_rn(x0, x1);
    hp = *reinterpret_cast<u32*>(&hh);
    float r0 = x0 - __low2float(hh);
    float r1 = x1 - __high2float(hh);
    __half2 ll = __floats2half2_rn(r0, r1);
    lp = *reinterpret_cast<u32*>(&ll);
}

// ---------------------------------------------------------------------------
// Conversion kernels (hi + lo bf16)
// ---------------------------------------------------------------------------
__global__ __launch_bounds__(256) void conv_split(
    const float* __restrict__ x, bf16* __restrict__ h, bf16* __restrict__ l, int n4)
{
    int i = blockIdx.x * 256 + threadIdx.x;
    if (i >= n4) return;
    float4 v = ((const float4*)x)[i];
    float vv[4] = {v.x, v.y, v.z, v.w};
    u16 hb[4], lb[4];
#pragma unroll
    for (int e = 0; e < 4; ++e) split2(vv[e], hb[e], lb[e]);
    ((uint2*)h)[i] = make_uint2(((u32)hb[1] << 16) | hb[0], ((u32)hb[3] << 16) | hb[2]);
    ((uint2*)l)[i] = make_uint2(((u32)lb[1] << 16) | lb[0], ((u32)lb[3] << 16) | lb[2]);
}

// W[k][n] fp32 -> Wt[n][k] split-bf16 (transpose through smem)
__global__ __launch_bounds__(256) void conv_wt(
    const float* __restrict__ W, bf16* __restrict__ Th, bf16* __restrict__ Tl)
{
    __shared__ float ts[32][33];
    int tx = threadIdx.x, ty = threadIdx.y;         // 32 x 8
    int x0 = blockIdx.x * 32, y0 = blockIdx.y * 32; // x: n, y: k
#pragma unroll
    for (int i = 0; i < 4; ++i)
        ts[ty + i * 8][tx] = W[(size_t)(y0 + ty + i * 8) * DMODEL + x0 + tx];
    __syncthreads();
#pragma unroll
    for (int i = 0; i < 4; ++i) {
        int n = x0 + ty + i * 8, k = y0 + tx;
        u16 h, l; split2(ts[tx][ty + i * 8], h, l);
        Th[(size_t)n * DMODEL + k] = *reinterpret_cast<bf16*>(&h);
        Tl[(size_t)n * DMODEL + k] = *reinterpret_cast<bf16*>(&l);
    }
}

// ---------------------------------------------------------------------------
// 3-product split-bf16 HMMA GEMM: C = Ah/Al @ (Bh/Bl)^T + bias
// Output: fp32 (Cf) | split-fp16 (Fh,Fl) | single fp16 (Fh, Fl==null).
// Block 128x128, K-chunk 64, cp.async 2-stage (2 x 64 KB smem).
// ---------------------------------------------------------------------------
#define G3_ISSUE(st, k0) do {                                                \
    u32 bs_ = sb + (u32)(st) * 65536u;                                       \
    _Pragma("unroll")                                                        \
    for (int it_ = 0; it_ < 4; ++it_) {                                      \
        int i_ = tid + it_ * 256;                                            \
        int row_ = i_ >> 3, c_ = i_ & 7;                                     \
        u32 so_ = SWZ((u32)(row_ * 128 + c_ * 16));                          \
        size_t ao_ = (size_t)(m0 + row_) * DMODEL + (k0) + c_ * 8;           \
        size_t bo_ = (size_t)(n0 + row_) * DMODEL + (k0) + c_ * 8;           \
        cpa16(bs_ + so_,          Ah + ao_);                                 \
        cpa16(bs_ + 16384u + so_, Al + ao_);                                 \
        cpa16(bs_ + 32768u + so_, Bh + bo_);                                 \
        cpa16(bs_ + 49152u + so_, Bl + bo_);                                 \
    }                                                                        \
    cpcommit();                                                              \
} while (0)

__global__ __launch_bounds__(256, 1) void gemm_mma(
    const bf16* __restrict__ Ah, const bf16* __restrict__ Al,
    const bf16* __restrict__ Bh, const bf16* __restrict__ Bl,
    const float* __restrict__ bias,
    float* __restrict__ Cf, half* __restrict__ Fh, half* __restrict__ Fl)
{
    extern __shared__ char sm[];
    const u32 sb = cvta_s(sm);
    const int tid = threadIdx.x, wid = tid >> 5, lane = tid & 31;
    const int n0 = blockIdx.x * 128, m0 = blockIdx.y * 128;
    const int wm = (wid >> 2) * 64, wn = (wid & 3) * 32;

    float acc[4][4][4];
#pragma unroll
    for (int mi = 0; mi < 4; ++mi)
#pragma unroll
        for (int nt = 0; nt < 4; ++nt)
#pragma unroll
            for (int e = 0; e < 4; ++e) acc[mi][nt][e] = 0.f;

    G3_ISSUE(0, 0);
    for (int kc = 0; kc < 16; ++kc) {
        if (kc < 15) G3_ISSUE((kc + 1) & 1, (kc + 1) * 64);
        if (kc < 15) cpwait1(); else cpwait0();
        __syncthreads();

        const u32 bs = sb + (u32)(kc & 1) * 65536u;
        const u32 sAh = bs, sAl = bs + 16384, sBh = bs + 32768, sBl = bs + 49152;

#pragma unroll
        for (int ks = 0; ks < 4; ++ks) {
            u32 ah[4][4], al[4][4];
#pragma unroll
            for (int mi = 0; mi < 4; ++mi) {
                u32 ad = SWZ((u32)((wm + mi * 16 + (lane & 15)) * 128 +
                                   ks * 32 + (lane >> 4) * 16));
                ldmx4(ah[mi][0], ah[mi][1], ah[mi][2], ah[mi][3], sAh + ad);
                ldmx4(al[mi][0], al[mi][1], al[mi][2], al[mi][3], sAl + ad);
            }
            u32 bh[4][2], bl[4][2];
#pragma unroll
            for (int nj = 0; nj < 2; ++nj) {
                u32 ad = SWZ((u32)((wn + nj * 16 + (lane & 15)) * 128 +
                                   ks * 32 + (lane >> 4) * 16));
                u32 r0, r1, r2, r3;
                ldmx4(r0, r1, r2, r3, sBh + ad);
                bh[2 * nj][0] = r0; bh[2 * nj][1] = r2;
                bh[2 * nj + 1][0] = r1; bh[2 * nj + 1][1] = r3;
                ldmx4(r0, r1, r2, r3, sBl + ad);
                bl[2 * nj][0] = r0; bl[2 * nj][1] = r2;
                bl[2 * nj + 1][0] = r1; bl[2 * nj + 1][1] = r3;
            }
#pragma unroll
            for (int mi = 0; mi < 4; ++mi)
#pragma unroll
                for (int nt = 0; nt < 4; ++nt) {
                    mma16816(acc[mi][nt], ah[mi], bh[nt]);
                    mma16816(acc[mi][nt], ah[mi], bl[nt]);
                    mma16816(acc[mi][nt], al[mi], bh[nt]);
                }
        }
        __syncthreads();
    }

    const int g = lane >> 2, tq = lane & 3;
#pragma unroll
    for (int mi = 0; mi < 4; ++mi) {
        int row0 = m0 + wm + mi * 16 + g;
#pragma unroll
        for (int nt = 0; nt < 4; ++nt) {
            int col = n0 + wn + nt * 8 + tq * 2;
            float b0 = bias[col], b1 = bias[col + 1];
            float v00 = acc[mi][nt][0] + b0, v01 = acc[mi][nt][1] + b1;
            float v10 = acc[mi][nt][2] + b0, v11 = acc[mi][nt][3] + b1;
            if (Cf) {
                *(float2*)(Cf + (size_t)row0 * DMODEL + col) = make_float2(v00, v01);
                *(float2*)(Cf + (size_t)(row0 + 8) * DMODEL + col) = make_float2(v10, v11);
            } else if (Fl) {
                u32 hp, lp;
                split_pack_h(v00, v01, hp, lp);
                *(u32*)(Fh + (size_t)row0 * DMODEL + col) = hp;
                *(u32*)(Fl + (size_t)row0 * DMODEL + col) = lp;
                split_pack_h(v10, v11, hp, lp);
                *(u32*)(Fh + (size_t)(row0 + 8) * DMODEL + col) = hp;
                *(u32*)(Fl + (size_t)(row0 + 8) * DMODEL + col) = lp;
            } else {
                *(u32*)(Fh + (size_t)row0 * DMODEL + col) = pack2h(v00, v01);
                *(u32*)(Fh + (size_t)(row0 + 8) * DMODEL + col) = pack2h(v10, v11);
            }
        }
    }
}

// ---------------------------------------------------------------------------
// fp16 HMMA flash attention, split-Q / split-P:
//   S  = Qh*K + Ql*K   (2 products; K fp16 single, Q split-fp16)
//   PV = Ph*V + Pl*V   (2 products; V fp16 single, P split-fp16 in regs)
// 128 q rows per CTA (8 warps x 16 rows), 64-row kv tiles, max-free softmax,
// O accumulated fp32 in registers, output split-bf16.
// smem: Qh/Ql 32 KB resident + 2 stages x [K 8K][V 8K] = 64 KB -> 2 CTAs/SM.
// ---------------------------------------------------------------------------
#define KVH_ISSUE(st, t) do {                                                \
    u32 bs_ = sb + 32768u + (u32)(st) * 16384u;                              \
    _Pragma("unroll")                                                        \
    for (int it_ = 0; it_ < 2; ++it_) {                                      \
        int i_ = tid + it_ * 256;                                            \
        int row_ = i_ >> 3, c_ = i_ & 7;                                     \
        u32 so_ = SWZ((u32)(row_ * 128 + c_ * 16));                          \
        size_t go_ = base + (size_t)((t) * 64 + row_) * DMODEL + c_ * 8;     \
        cpa16(bs_ + so_,         Kh_ + go_);                                 \
        cpa16(bs_ + 8192u + so_, Vh_ + go_);                                 \
    }                                                                        \
    cpcommit();                                                              \
} while (0)

__global__ __launch_bounds__(256, 2) void flash_h(
    const half* __restrict__ Qh_, const half* __restrict__ Ql_,
    const half* __restrict__ Kh_, const half* __restrict__ Vh_,
    bf16* __restrict__ Oh_, bf16* __restrict__ Ol_)
{
    extern __shared__ char sm[];
    const u32 sb = cvta_s(sm);
    const u32 sQh = sb, sQl = sb + 16384;
    const int tid = threadIdx.x, wid = tid >> 5, lane = tid & 31;
    const int b = blockIdx.z, h = blockIdx.y, q0 = blockIdx.x * 128;
    const size_t base = ((size_t)b * SEQ) * DMODEL + (size_t)h * DK;

    // Load Q (128 x 64, hi+lo fp16) and prefetch first K/V tile
#pragma unroll
    for (int it = 0; it < 4; ++it) {
        int i = tid + it * 256;
        int row = i >> 3, c = i & 7;
        u32 so = SWZ((u32)(row * 128 + c * 16));
        size_t go = base + (size_t)(q0 + row) * DMODEL + c * 8;
        sts128(sQh + so, *(const uint4*)(Qh_ + go));
        sts128(sQl + so, *(const uint4*)(Ql_ + go));
    }
    KVH_ISSUE(0, 0);
    __syncthreads();

    // Preload Qh fragments (stable); Ql reloaded per ks to save registers
    u32 qh[4][4];
#pragma unroll
    for (int ks = 0; ks < 4; ++ks) {
        u32 ad = SWZ((u32)((wid * 16 + (lane & 15)) * 128 +
                           ks * 32 + (lane >> 4) * 16));
        ldmx4(qh[ks][0], qh[ks][1], qh[ks][2], qh[ks][3], sQh + ad);
    }

    float oc[8][4];
#pragma unroll
    for (int nt = 0; nt < 8; ++nt)
#pragma unroll
        for (int e = 0; e < 4; ++e) oc[nt][e] = 0.f;
    float rs0 = 0.f, rs1 = 0.f;

    for (int t = 0; t < 32; ++t) {
        if (t < 31) KVH_ISSUE((t + 1) & 1, t + 1);
        if (t < 31) cpwait1(); else cpwait0();
        __syncthreads();

        const u32 bs = sb + 32768u + (u32)(t & 1) * 16384u;
        const u32 sK = bs, sV = bs + 8192u;

        // ---- S = Qh K^T + Ql K^T ----
        float sc[8][4];
#pragma unroll
        for (int nt = 0; nt < 8; ++nt)
#pragma unroll
            for (int e = 0; e < 4; ++e) sc[nt][e] = 0.f;

#pragma unroll
        for (int ks = 0; ks < 4; ++ks) {
            u32 kh[8][2];
#pragma unroll
            for (int nj = 0; nj < 4; ++nj) {
                u32 ad = SWZ((u32)((nj * 16 + (lane & 15)) * 128 +
                                   ks * 32 + (lane >> 4) * 16));
                u32 r0, r1, r2, r3;
                ldmx4(r0, r1, r2, r3, sK + ad);
                kh[2 * nj][0] = r0; kh[2 * nj][1] = r2;
                kh[2 * nj + 1][0] = r1; kh[2 * nj + 1][1] = r3;
            }
            u32 qlf[4];
            {
                u32 ad = SWZ((u32)((wid * 16 + (lane & 15)) * 128 +
                                   ks * 32 + (lane >> 4) * 16));
                ldmx4(qlf[0], qlf[1], qlf[2], qlf[3], sQl + ad);
            }
#pragma unroll
            for (int nt = 0; nt < 8; ++nt) {
                mma16816h(sc[nt], qh[ks], kh[nt]);
                mma16816h(sc[nt], qlf,    kh[nt]);
            }
        }

        // ---- exp (max-free) + row-sum accumulation ----
#pragma unroll
        for (int nt = 0; nt < 8; ++nt) {
#pragma unroll
            for (int e = 0; e < 4; ++e) sc[nt][e] = __expf(sc[nt][e] * 0.125f);
            rs0 += sc[nt][0] + sc[nt][1];
            rs1 += sc[nt][2] + sc[nt][3];
        }

        // ---- O += Ph V + Pl V  (P split-fp16 from S frags; V via trans) ----
#pragma unroll
        for (int ks = 0; ks < 4; ++ks) {
            const int j0 = 2 * ks, j1 = 2 * ks + 1;
            u32 ph[4], pl[4];
            split_pack_h(sc[j0][0], sc[j0][1], ph[0], pl[0]);
            split_pack_h(sc[j0][2], sc[j0][3], ph[1], pl[1]);
            split_pack_h(sc[j1][0], sc[j1][1], ph[2], pl[2]);
            split_pack_h(sc[j1][2], sc[j1][3], ph[3], pl[3]);

            u32 vh[8][2];
#pragma unroll
            for (int dj = 0; dj < 4; ++dj) {
                u32 ad = SWZ((u32)((ks * 16 + (lane & 15)) * 128 +
                                   dj * 32 + (lane >> 4) * 16));
                u32 r0, r1, r2, r3;
                ldmx4t(r0, r1, r2, r3, sV + ad);
                vh[2 * dj][0] = r0; vh[2 * dj][1] = r1;
                vh[2 * dj + 1][0] = r2; vh[2 * dj + 1][1] = r3;
            }
#pragma unroll
            for (int nt = 0; nt < 8; ++nt) {
                mma16816h(oc[nt], ph, vh[nt]);
                mma16816h(oc[nt], pl, vh[nt]);
            }
        }
        __syncthreads();
    }

    // ---- epilogue: row-sum reduce, normalize, split-bf16 store ----
    rs0 += __shfl_xor_sync(0xffffffffu, rs0, 1);
    rs0 += __shfl_xor_sync(0xffffffffu, rs0, 2);
    rs1 += __shfl_xor_sync(0xffffffffu, rs1, 1);
    rs1 += __shfl_xor_sync(0xffffffffu, rs1, 2);
    const float inv0 = 1.f / rs0, inv1 = 1.f / rs1;

    const int g = lane >> 2, tq = lane & 3;
    const int row0 = q0 + wid * 16 + g;
#pragma unroll
    for (int nt = 0; nt < 8; ++nt) {
        int col = nt * 8 + tq * 2;
        u32 hp, lp;
        split_pack(oc[nt][0] * inv0, oc[nt][1] * inv0, hp, lp);
        *(u32*)(Oh_ + base + (size_t)row0 * DMODEL + col) = hp;
        *(u32*)(Ol_ + base + (size_t)row0 * DMODEL + col) = lp;
        split_pack(oc[nt][2] * inv1, oc[nt][3] * inv1, hp, lp);
        *(u32*)(Oh_ + base + (size_t)(row0 + 8) * DMODEL + col) = hp;
        *(u32*)(Ol_ + base + (size_t)(row0 + 8) * DMODEL + col) = lp;
    }
}

// ---------------------------------------------------------------------------
// Launch
// ---------------------------------------------------------------------------
extern "C" void kernel_launch(void* const* d_in, const int* in_sizes, int n_in,
                              void* d_out, int out_size)
{
    const float* query = (const float*)d_in[0];
    const float* key   = (const float*)d_in[1];
    const float* value = (const float*)d_in[2];
    const float* Wq = (const float*)d_in[3];
    const float* bq = (const float*)d_in[4];
    const float* Wk = (const float*)d_in[5];
    const float* bk = (const float*)d_in[6];
    const float* Wv = (const float*)d_in[7];
    const float* bv = (const float*)d_in[8];
    const float* Wo = (const float*)d_in[9];
    const float* bo = (const float*)d_in[10];
    float* out = (float*)d_out;

    bf16 *act, *obuf, *wbuf;
    half *prjh;
    cudaGetSymbolAddress((void**)&act,  g_act);
    cudaGetSymbolAddress((void**)&prjh, g_prjh);
    cudaGetSymbolAddress((void**)&obuf, g_o);
    cudaGetSymbolAddress((void**)&wbuf, g_w);

    bf16 *aq_h = act,          *aq_l = act + SZ;
    bf16 *ak_h = act + 2 * SZ, *ak_l = act + 3 * SZ;
    bf16 *av_h = act + 4 * SZ, *av_l = act + 5 * SZ;
    half *q_h = prjh, *q_l = prjh + SZ, *k_h = prjh + 2 * SZ, *v_h = prjh + 3 * SZ;
    bf16 *o_h = obuf, *o_l = obuf + SZ;
    bf16 *wq_h = wbuf,           *wq_l = wbuf + WSZ;
    bf16 *wk_h = wbuf + 2 * WSZ, *wk_l = wbuf + 3 * WSZ;
    bf16 *wv_h = wbuf + 4 * WSZ, *wv_l = wbuf + 5 * WSZ;
    bf16 *wo_h = wbuf + 6 * WSZ, *wo_l = wbuf + 7 * WSZ;

    const int n4 = (int)(SZ / 4);
    conv_split<<<(n4 + 255) / 256, 256>>>(query, aq_h, aq_l, n4);
    conv_split<<<(n4 + 255) / 256, 256>>>(key,   ak_h, ak_l, n4);
    conv_split<<<(n4 + 255) / 256, 256>>>(value, av_h, av_l, n4);
    dim3 wtg(32, 32), wtb(32, 8);
    conv_wt<<<wtg, wtb>>>(Wq, wq_h, wq_l);
    conv_wt<<<wtg, wtb>>>(Wk, wk_h, wk_l);
    conv_wt<<<wtg, wtb>>>(Wv, wv_h, wv_l);
    conv_wt<<<wtg, wtb>>>(Wo, wo_h, wo_l);

    const int gsm = 131072;   // 2 stages x 64 KB
    cudaFuncSetAttribute(gemm_mma, cudaFuncAttributeMaxDynamicSharedMemorySize, gsm);
    dim3 ggrid(DMODEL / 128, MROWS / 128);   // (8, 64)
    gemm_mma<<<ggrid, 256, gsm>>>(aq_h, aq_l, wq_h, wq_l, bq, nullptr, q_h, q_l);
    gemm_mma<<<ggrid, 256, gsm>>>(ak_h, ak_l, wk_h, wk_l, bk, nullptr, k_h, nullptr);
    gemm_mma<<<ggrid, 256, gsm>>>(av_h, av_l, wv_h, wv_l, bv, nullptr, v_h, nullptr);

    const int fsm = 65536;    // Qh/Ql 32 KB + 2 stages x 16 KB -> 2 CTAs/SM
    cudaFuncSetAttribute(flash_h, cudaFuncAttributeMaxDynamicSharedMemorySize, fsm);
    dim3 fgrid(SEQ / 128, NHEADS, BATCH);    // (16, 16, 4)
    flash_h<<<fgrid, 256, fsm>>>(q_h, q_l, k_h, v_h, o_h, o_l);

    gemm_mma<<<ggrid, 256, gsm>>>(o_h, o_l, wo_h, wo_l, bo, out, nullptr, nullptr);
}